// round 1
// baseline (speedup 1.0000x reference)
#include <cuda_runtime.h>
#include <math.h>
#include <stdint.h>

#define NN 50000
#define EE 800000
#define GNN_IN 256
#define HID 512
#define F_DIM 128
#define HC 256
#define NCLS 40

// ---------------- scratch (device globals; no allocation allowed) ----------
__device__ float g_q[(size_t)NN * HC];
__device__ float g_k[(size_t)NN * HC];
__device__ float g_v[(size_t)NN * HC];
__device__ float g_hg[(size_t)NN * HC];    // skip + aggregated messages
__device__ float g_hm[(size_t)NN * HC];    // MLP branch output
__device__ float g_h1[(size_t)NN * HID];   // reused for classifier hidden
__device__ float g_h2[(size_t)NN * HID];
__device__ float g_logit[(size_t)EE * 2];
__device__ float g_ex[(size_t)EE * 2];
__device__ unsigned g_amax[(size_t)NN * 2];
__device__ float g_amaxf[(size_t)NN * 2];
__device__ float g_denom[(size_t)NN * 2];
__device__ float g_sum1[HID], g_sumsq1[HID], g_sum2[HID], g_sumsq2[HID];
__device__ float g_mu1[HID], g_rsig1[HID], g_mu2[HID], g_rsig2[HID];

// ---------------- helpers --------------------------------------------------
__device__ __forceinline__ unsigned encF(float f) {
    unsigned u = __float_as_uint(f);
    return (u & 0x80000000u) ? ~u : (u | 0x80000000u);
}
__device__ __forceinline__ float decF(unsigned u) {
    return (u & 0x80000000u) ? __uint_as_float(u ^ 0x80000000u) : __uint_as_float(~u);
}
__device__ __forceinline__ void redAdd4(float* p, float a, float b, float c, float d) {
    asm volatile("red.global.add.v4.f32 [%0], {%1,%2,%3,%4};"
                 :: "l"(p), "f"(a), "f"(b), "f"(c), "f"(d) : "memory");
}

// ---------------- init -----------------------------------------------------
__global__ void init_kernel() {
    int i = blockIdx.x * blockDim.x + threadIdx.x;
    if (i < NN * 2) {
        g_amax[i] = 0x007FFFFFu;   // enc(-inf)
        g_denom[i] = 0.f;
    }
    if (i < HID) {
        g_sum1[i] = 0.f; g_sumsq1[i] = 0.f;
        g_sum2[i] = 0.f; g_sumsq2[i] = 0.f;
    }
}

// ---------------- SGEMM: C[M,N] = A[M,K] @ B[N,K]^T + bias ------------------
// act: 0 = none, 1 = relu
__global__ void __launch_bounds__(256)
sgemm_nt(const float* __restrict__ A, const float* __restrict__ B,
         const float* __restrict__ bias, float* __restrict__ C,
         int M, int N, int K, int act)
{
    __shared__ float As[16][132];
    __shared__ float Bs[16][132];
    const int tid = threadIdx.x;
    const int m0 = blockIdx.y * 128;
    const int n0 = blockIdx.x * 128;
    const int tm = (tid >> 4) << 3;
    const int tn = (tid & 15) << 3;

    float acc[8][8];
#pragma unroll
    for (int i = 0; i < 8; i++)
#pragma unroll
        for (int j = 0; j < 8; j++) acc[i][j] = 0.f;

    const int lr = tid >> 2;          // 0..63
    const int lk = (tid & 3) << 2;    // 0,4,8,12

    for (int k0 = 0; k0 < K; k0 += 16) {
#pragma unroll
        for (int s = 0; s < 2; s++) {
            int row = m0 + lr + s * 64;
            float4 av = make_float4(0.f, 0.f, 0.f, 0.f);
            if (row < M) av = *(const float4*)(A + (size_t)row * K + k0 + lk);
            As[lk + 0][lr + s * 64] = av.x;
            As[lk + 1][lr + s * 64] = av.y;
            As[lk + 2][lr + s * 64] = av.z;
            As[lk + 3][lr + s * 64] = av.w;
            int col = n0 + lr + s * 64;
            float4 bv = make_float4(0.f, 0.f, 0.f, 0.f);
            if (col < N) bv = *(const float4*)(B + (size_t)col * K + k0 + lk);
            Bs[lk + 0][lr + s * 64] = bv.x;
            Bs[lk + 1][lr + s * 64] = bv.y;
            Bs[lk + 2][lr + s * 64] = bv.z;
            Bs[lk + 3][lr + s * 64] = bv.w;
        }
        __syncthreads();
#pragma unroll
        for (int kk = 0; kk < 16; kk++) {
            float a[8], b[8];
#pragma unroll
            for (int i = 0; i < 8; i++) a[i] = As[kk][tm + i];
#pragma unroll
            for (int j = 0; j < 8; j++) b[j] = Bs[kk][tn + j];
#pragma unroll
            for (int i = 0; i < 8; i++)
#pragma unroll
                for (int j = 0; j < 8; j++) acc[i][j] = fmaf(a[i], b[j], acc[i][j]);
        }
        __syncthreads();
    }

#pragma unroll
    for (int i = 0; i < 8; i++) {
        int row = m0 + tm + i;
        if (row >= M) continue;
#pragma unroll
        for (int j = 0; j < 8; j++) {
            int col = n0 + tn + j;
            if (col >= N) continue;
            float vv = acc[i][j] + bias[col];
            if (act == 1) vv = fmaxf(vv, 0.f);
            C[(size_t)row * N + col] = vv;
        }
    }
}

// ---------------- edge kernels ----------------------------------------------
__global__ void __launch_bounds__(256)
edge_logits(const int* __restrict__ ei)
{
    int e = blockIdx.x * 8 + (threadIdx.x >> 5);
    if (e >= EE) return;
    int lane = threadIdx.x & 31;
    int src = ei[e];
    int dst = ei[EE + e];
#pragma unroll
    for (int h = 0; h < 2; h++) {
        float4 qv = *(const float4*)(g_q + (size_t)dst * HC + h * F_DIM + lane * 4);
        float4 kv = *(const float4*)(g_k + (size_t)src * HC + h * F_DIM + lane * 4);
        float d = qv.x * kv.x + qv.y * kv.y + qv.z * kv.z + qv.w * kv.w;
#pragma unroll
        for (int off = 16; off; off >>= 1) d += __shfl_xor_sync(0xFFFFFFFFu, d, off);
        d *= 0.08838834764831845f; // 1/sqrt(128)
        if (lane == 0) {
            g_logit[(size_t)e * 2 + h] = d;
            atomicMax(&g_amax[(size_t)dst * 2 + h], encF(d));
        }
    }
}

__global__ void decode_amax() {
    int i = blockIdx.x * blockDim.x + threadIdx.x;
    if (i >= NN * 2) return;
    float d = decF(g_amax[i]);
    g_amaxf[i] = isfinite(d) ? d : 0.f;
}

__global__ void edge_exp(const int* __restrict__ ei) {
    int idx = blockIdx.x * blockDim.x + threadIdx.x;
    if (idx >= EE * 2) return;
    int e = idx >> 1, h = idx & 1;
    int dst = ei[EE + e];
    float ex = expf(g_logit[idx] - g_amaxf[(size_t)dst * 2 + h]);
    g_ex[idx] = ex;
    atomicAdd(&g_denom[(size_t)dst * 2 + h], ex);
}

__global__ void __launch_bounds__(256)
edge_aggregate(const int* __restrict__ ei)
{
    int e = blockIdx.x * 8 + (threadIdx.x >> 5);
    if (e >= EE) return;
    int lane = threadIdx.x & 31;
    int src = ei[e];
    int dst = ei[EE + e];
    int h = lane >> 4;               // lanes 0-15 head0, 16-31 head1
    int c = (lane & 15) * 8;         // 8 floats per lane
    float attn = g_ex[(size_t)e * 2 + h] /
                 fmaxf(g_denom[(size_t)dst * 2 + h], 1e-16f);
    const float4* vp = (const float4*)(g_v + (size_t)src * HC + h * F_DIM + c);
    float* hp = g_hg + (size_t)dst * HC + h * F_DIM + c;
    float4 v0 = vp[0], v1 = vp[1];
    redAdd4(hp,     v0.x * attn, v0.y * attn, v0.z * attn, v0.w * attn);
    redAdd4(hp + 4, v1.x * attn, v1.y * attn, v1.z * attn, v1.w * attn);
}

// ---------------- batchnorm -------------------------------------------------
__global__ void __launch_bounds__(256)
col_stats(const float* __restrict__ X, float* __restrict__ sum, float* __restrict__ sumsq)
{
    int col = blockIdx.x * 256 + threadIdx.x;   // gridDim.x = HID/256 = 2
    float s = 0.f, sq = 0.f;
    for (int r = blockIdx.y; r < NN; r += gridDim.y) {
        float x = X[(size_t)r * HID + col];
        s += x;
        sq = fmaf(x, x, sq);
    }
    atomicAdd(&sum[col], s);
    atomicAdd(&sumsq[col], sq);
}

__global__ void bn_finalize(const float* __restrict__ sum, const float* __restrict__ sumsq,
                            float* __restrict__ mu, float* __restrict__ rsig)
{
    int c = threadIdx.x + blockIdx.x * blockDim.x;
    if (c >= HID) return;
    float m = sum[c] * (1.f / NN);
    float var = sumsq[c] * (1.f / NN) - m * m;
    mu[c] = m;
    rsig[c] = rsqrtf(var + 1e-5f);
}

__global__ void bn_apply_sigmoid(float* __restrict__ X,
                                 const float* __restrict__ mu, const float* __restrict__ rsig,
                                 const float* __restrict__ g, const float* __restrict__ be)
{
    size_t i = (size_t)blockIdx.x * blockDim.x + threadIdx.x;
    if (i >= (size_t)NN * HID) return;
    int c = (int)(i & (HID - 1));
    float x = X[i];
    float y = (x - mu[c]) * rsig[c] * g[c] + be[c];
    X[i] = 1.f / (1.f + expf(-y));
}

// ---------------- fusion ----------------------------------------------------
__global__ void fuse_kernel(const float* __restrict__ alpha, const float* __restrict__ beta)
{
    size_t i = (size_t)blockIdx.x * blockDim.x + threadIdx.x;
    if (i >= (size_t)NN * HC) return;
    g_hg[i] = alpha[0] * g_hg[i] + beta[0] * g_hm[i];
}

// ---------------- launch ----------------------------------------------------
extern "C" void kernel_launch(void* const* d_in, const int* in_sizes, int n_in,
                              void* d_out, int out_size)
{
    const float* x_gsage = (const float*)d_in[0];
    const int*   ei      = (const int*)d_in[1];
    const float* x_mlp   = (const float*)d_in[2];
    const float* Wq = (const float*)d_in[3];  const float* bq = (const float*)d_in[4];
    const float* Wk = (const float*)d_in[5];  const float* bk = (const float*)d_in[6];
    const float* Wv = (const float*)d_in[7];  const float* bv = (const float*)d_in[8];
    const float* Ws = (const float*)d_in[9];  const float* bs = (const float*)d_in[10];
    const float* W1 = (const float*)d_in[11]; const float* b1 = (const float*)d_in[12];
    const float* g1 = (const float*)d_in[13]; const float* be1 = (const float*)d_in[14];
    const float* W2 = (const float*)d_in[15]; const float* b2 = (const float*)d_in[16];
    const float* g2 = (const float*)d_in[17]; const float* be2 = (const float*)d_in[18];
    const float* W3 = (const float*)d_in[19]; const float* b3 = (const float*)d_in[20];
    const float* alpha = (const float*)d_in[21];
    const float* beta  = (const float*)d_in[22];
    const float* Wc1 = (const float*)d_in[23]; const float* bc1 = (const float*)d_in[24];
    const float* Wc2 = (const float*)d_in[25]; const float* bc2 = (const float*)d_in[26];
    float* out = (float*)d_out;

    float *q, *k, *v, *hg, *hm, *h1, *h2;
    float *sum1, *sumsq1, *sum2, *sumsq2, *mu1, *rsig1, *mu2, *rsig2;
    cudaGetSymbolAddress((void**)&q,  g_q);
    cudaGetSymbolAddress((void**)&k,  g_k);
    cudaGetSymbolAddress((void**)&v,  g_v);
    cudaGetSymbolAddress((void**)&hg, g_hg);
    cudaGetSymbolAddress((void**)&hm, g_hm);
    cudaGetSymbolAddress((void**)&h1, g_h1);
    cudaGetSymbolAddress((void**)&h2, g_h2);
    cudaGetSymbolAddress((void**)&sum1, g_sum1);
    cudaGetSymbolAddress((void**)&sumsq1, g_sumsq1);
    cudaGetSymbolAddress((void**)&sum2, g_sum2);
    cudaGetSymbolAddress((void**)&sumsq2, g_sumsq2);
    cudaGetSymbolAddress((void**)&mu1, g_mu1);
    cudaGetSymbolAddress((void**)&rsig1, g_rsig1);
    cudaGetSymbolAddress((void**)&mu2, g_mu2);
    cudaGetSymbolAddress((void**)&rsig2, g_rsig2);

    dim3 blk(256);

    // init accumulators
    init_kernel<<<(NN * 2 + 255) / 256, blk>>>();

    // projections
    dim3 g256(HC / 128, (NN + 127) / 128);
    sgemm_nt<<<g256, blk>>>(x_gsage, Wq, bq, q,  NN, HC, GNN_IN, 0);
    sgemm_nt<<<g256, blk>>>(x_gsage, Wk, bk, k,  NN, HC, GNN_IN, 0);
    sgemm_nt<<<g256, blk>>>(x_gsage, Wv, bv, v,  NN, HC, GNN_IN, 0);
    sgemm_nt<<<g256, blk>>>(x_gsage, Ws, bs, hg, NN, HC, GNN_IN, 0);

    // attention
    edge_logits<<<(EE + 7) / 8, blk>>>(ei);
    decode_amax<<<(NN * 2 + 255) / 256, blk>>>();
    edge_exp<<<(EE * 2 + 255) / 256, blk>>>(ei);
    edge_aggregate<<<(EE + 7) / 8, blk>>>(ei);

    // MLP branch
    dim3 g512(HID / 128, (NN + 127) / 128);
    sgemm_nt<<<g512, blk>>>(x_mlp, W1, b1, h1, NN, HID, GNN_IN, 0);
    col_stats<<<dim3(HID / 256, 128), blk>>>(h1, sum1, sumsq1);
    bn_finalize<<<2, blk>>>(sum1, sumsq1, mu1, rsig1);
    bn_apply_sigmoid<<<((size_t)NN * HID + 255) / 256, blk>>>(h1, mu1, rsig1, g1, be1);

    sgemm_nt<<<g512, blk>>>(h1, W2, b2, h2, NN, HID, HID, 0);
    col_stats<<<dim3(HID / 256, 128), blk>>>(h2, sum2, sumsq2);
    bn_finalize<<<2, blk>>>(sum2, sumsq2, mu2, rsig2);
    bn_apply_sigmoid<<<((size_t)NN * HID + 255) / 256, blk>>>(h2, mu2, rsig2, g2, be2);

    sgemm_nt<<<g256, blk>>>(h2, W3, b3, hm, NN, HC, HID, 0);

    // fuse
    fuse_kernel<<<((size_t)NN * HC + 255) / 256, blk>>>(alpha, beta);

    // classifier head (reuse h1 as hidden)
    sgemm_nt<<<g512, blk>>>(hg, Wc1, bc1, h1, NN, HID, HC, 1);
    sgemm_nt<<<dim3(1, (NN + 127) / 128), blk>>>(h1, Wc2, bc2, out, NN, NCLS, HID, 0);
}

// round 2
// speedup vs baseline: 2.1662x; 2.1662x over previous
#include <cuda_runtime.h>
#include <math.h>
#include <stdint.h>

#define NN 50000
#define EE 800000
#define GNN_IN 256
#define HID 512
#define F_DIM 128
#define HC 256
#define NCLS 40

// ---------------- scratch (device globals; no allocation allowed) ----------
__device__ float g_q[(size_t)NN * HC];
__device__ float g_k[(size_t)NN * HC];
__device__ float g_v[(size_t)NN * HC];
__device__ float g_hg[(size_t)NN * HC];    // skip + aggregated messages
__device__ float g_hm[(size_t)NN * HC];    // MLP branch output
__device__ float g_h1[(size_t)NN * HID];   // reused for classifier hidden
__device__ float g_h2[(size_t)NN * HID];
__device__ float g_logit[(size_t)EE * 2];
__device__ float g_ex[(size_t)EE * 2];
__device__ unsigned g_amax[(size_t)NN * 2];
__device__ float g_amaxf[(size_t)NN * 2];
__device__ float g_denom[(size_t)NN * 2];
__device__ float g_sum1[HID], g_sumsq1[HID], g_sum2[HID], g_sumsq2[HID];
__device__ float g_mu1[HID], g_rsig1[HID], g_mu2[HID], g_rsig2[HID];

// ---------------- helpers --------------------------------------------------
__device__ __forceinline__ unsigned encF(float f) {
    unsigned u = __float_as_uint(f);
    return (u & 0x80000000u) ? ~u : (u | 0x80000000u);
}
__device__ __forceinline__ float decF(unsigned u) {
    return (u & 0x80000000u) ? __uint_as_float(u ^ 0x80000000u) : __uint_as_float(~u);
}
__device__ __forceinline__ void redAdd4(float* p, float a, float b, float c, float d) {
    asm volatile("red.global.add.v4.f32 [%0], {%1,%2,%3,%4};"
                 :: "l"(p), "f"(a), "f"(b), "f"(c), "f"(d) : "memory");
}
__device__ __forceinline__ unsigned f2tf(float f) {
    unsigned r;
    asm("cvt.rna.tf32.f32 %0, %1;" : "=r"(r) : "f"(f));
    return r;
}

// ---------------- init -----------------------------------------------------
__global__ void init_kernel() {
    int i = blockIdx.x * blockDim.x + threadIdx.x;
    if (i < NN * 2) {
        g_amax[i] = 0x007FFFFFu;   // enc(-inf)
        g_denom[i] = 0.f;
    }
    if (i < HID) {
        g_sum1[i] = 0.f; g_sumsq1[i] = 0.f;
        g_sum2[i] = 0.f; g_sumsq2[i] = 0.f;
    }
}

// ---------------- tensor-core GEMM: C[M,N] = A[M,K] @ B[N,K]^T + bias ------
// tf32 mma.sync m16n8k8. Block tile 128x128, BK=32, 8 warps (warp tile 32x64).
// act: 0 = none, 1 = relu
__global__ void __launch_bounds__(256, 2)
gemm_tf32(const float* __restrict__ A, const float* __restrict__ B,
          const float* __restrict__ bias, float* __restrict__ C,
          int M, int N, int K, int act)
{
    __shared__ float As[128][36];
    __shared__ float Bs[128][36];

    const int tid  = threadIdx.x;
    const int m0   = blockIdx.y * 128;
    const int n0   = blockIdx.x * 128;
    const int lane = tid & 31;
    const int w    = tid >> 5;
    const int wm   = (w & 3) * 32;   // warp M offset
    const int wn   = (w >> 2) * 64;  // warp N offset
    const int g    = lane >> 2;      // group id 0..7
    const int tg   = lane & 3;       // thread-in-group 0..3

    float acc[2][8][4];
#pragma unroll
    for (int mi = 0; mi < 2; mi++)
#pragma unroll
        for (int nj = 0; nj < 8; nj++)
#pragma unroll
            for (int q = 0; q < 4; q++) acc[mi][nj][q] = 0.f;

    const int cr = tid >> 3;        // 0..31 copy row
    const int cc = (tid & 7) * 4;   // copy col (float4)

    for (int k0 = 0; k0 < K; k0 += 32) {
#pragma unroll
        for (int it = 0; it < 4; it++) {
            int r = cr + it * 32;
            // A tile
            {
                int grow = m0 + r;
                float4 v = make_float4(0.f, 0.f, 0.f, 0.f);
                if (grow < M) v = *(const float4*)(A + (size_t)grow * K + k0 + cc);
                uint4 t;
                t.x = f2tf(v.x); t.y = f2tf(v.y); t.z = f2tf(v.z); t.w = f2tf(v.w);
                *(uint4*)&As[r][cc] = t;
            }
            // B tile
            {
                int nrow = n0 + r;
                float4 v = make_float4(0.f, 0.f, 0.f, 0.f);
                if (nrow < N) v = *(const float4*)(B + (size_t)nrow * K + k0 + cc);
                uint4 t;
                t.x = f2tf(v.x); t.y = f2tf(v.y); t.z = f2tf(v.z); t.w = f2tf(v.w);
                *(uint4*)&Bs[r][cc] = t;
            }
        }
        __syncthreads();

#pragma unroll
        for (int ks = 0; ks < 4; ks++) {
            const int kk = ks * 8;
            unsigned a[2][4], b[8][2];
#pragma unroll
            for (int mi = 0; mi < 2; mi++) {
                a[mi][0] = __float_as_uint(As[wm + mi * 16 + g][kk + tg]);
                a[mi][1] = __float_as_uint(As[wm + mi * 16 + g + 8][kk + tg]);
                a[mi][2] = __float_as_uint(As[wm + mi * 16 + g][kk + tg + 4]);
                a[mi][3] = __float_as_uint(As[wm + mi * 16 + g + 8][kk + tg + 4]);
            }
#pragma unroll
            for (int nj = 0; nj < 8; nj++) {
                b[nj][0] = __float_as_uint(Bs[wn + nj * 8 + g][kk + tg]);
                b[nj][1] = __float_as_uint(Bs[wn + nj * 8 + g][kk + tg + 4]);
            }
#pragma unroll
            for (int mi = 0; mi < 2; mi++)
#pragma unroll
                for (int nj = 0; nj < 8; nj++) {
                    asm volatile(
                        "mma.sync.aligned.m16n8k8.row.col.f32.tf32.tf32.f32 "
                        "{%0,%1,%2,%3}, {%4,%5,%6,%7}, {%8,%9}, {%0,%1,%2,%3};"
                        : "+f"(acc[mi][nj][0]), "+f"(acc[mi][nj][1]),
                          "+f"(acc[mi][nj][2]), "+f"(acc[mi][nj][3])
                        : "r"(a[mi][0]), "r"(a[mi][1]), "r"(a[mi][2]), "r"(a[mi][3]),
                          "r"(b[nj][0]), "r"(b[nj][1]));
                }
        }
        __syncthreads();
    }

    // epilogue: bias (+ optional relu), float2 stores
#pragma unroll
    for (int mi = 0; mi < 2; mi++) {
        int r0 = m0 + wm + mi * 16 + g;
        int r1 = r0 + 8;
#pragma unroll
        for (int nj = 0; nj < 8; nj++) {
            int col = n0 + wn + nj * 8 + 2 * tg;
            if (col >= N) continue;
            float bx = bias[col], by = bias[col + 1];
            if (r0 < M) {
                float ox = acc[mi][nj][0] + bx;
                float oy = acc[mi][nj][1] + by;
                if (act == 1) { ox = fmaxf(ox, 0.f); oy = fmaxf(oy, 0.f); }
                *(float2*)(C + (size_t)r0 * N + col) = make_float2(ox, oy);
            }
            if (r1 < M) {
                float ox = acc[mi][nj][2] + bx;
                float oy = acc[mi][nj][3] + by;
                if (act == 1) { ox = fmaxf(ox, 0.f); oy = fmaxf(oy, 0.f); }
                *(float2*)(C + (size_t)r1 * N + col) = make_float2(ox, oy);
            }
        }
    }
}

// ---------------- edge kernels ----------------------------------------------
__global__ void __launch_bounds__(256)
edge_logits(const int* __restrict__ ei)
{
    int e = blockIdx.x * 8 + (threadIdx.x >> 5);
    if (e >= EE) return;
    int lane = threadIdx.x & 31;
    int src = ei[e];
    int dst = ei[EE + e];
#pragma unroll
    for (int h = 0; h < 2; h++) {
        float4 qv = *(const float4*)(g_q + (size_t)dst * HC + h * F_DIM + lane * 4);
        float4 kv = *(const float4*)(g_k + (size_t)src * HC + h * F_DIM + lane * 4);
        float d = qv.x * kv.x + qv.y * kv.y + qv.z * kv.z + qv.w * kv.w;
#pragma unroll
        for (int off = 16; off; off >>= 1) d += __shfl_xor_sync(0xFFFFFFFFu, d, off);
        d *= 0.08838834764831845f; // 1/sqrt(128)
        if (lane == 0) {
            g_logit[(size_t)e * 2 + h] = d;
            atomicMax(&g_amax[(size_t)dst * 2 + h], encF(d));
        }
    }
}

__global__ void decode_amax() {
    int i = blockIdx.x * blockDim.x + threadIdx.x;
    if (i >= NN * 2) return;
    float d = decF(g_amax[i]);
    g_amaxf[i] = isfinite(d) ? d : 0.f;
}

__global__ void edge_exp(const int* __restrict__ ei) {
    int idx = blockIdx.x * blockDim.x + threadIdx.x;
    if (idx >= EE * 2) return;
    int e = idx >> 1, h = idx & 1;
    int dst = ei[EE + e];
    float ex = expf(g_logit[idx] - g_amaxf[(size_t)dst * 2 + h]);
    g_ex[idx] = ex;
    atomicAdd(&g_denom[(size_t)dst * 2 + h], ex);
}

__global__ void __launch_bounds__(256)
edge_aggregate(const int* __restrict__ ei)
{
    int e = blockIdx.x * 8 + (threadIdx.x >> 5);
    if (e >= EE) return;
    int lane = threadIdx.x & 31;
    int src = ei[e];
    int dst = ei[EE + e];
    int h = lane >> 4;               // lanes 0-15 head0, 16-31 head1
    int c = (lane & 15) * 8;         // 8 floats per lane
    float attn = g_ex[(size_t)e * 2 + h] /
                 fmaxf(g_denom[(size_t)dst * 2 + h], 1e-16f);
    const float4* vp = (const float4*)(g_v + (size_t)src * HC + h * F_DIM + c);
    float* hp = g_hg + (size_t)dst * HC + h * F_DIM + c;
    float4 v0 = vp[0], v1 = vp[1];
    redAdd4(hp,     v0.x * attn, v0.y * attn, v0.z * attn, v0.w * attn);
    redAdd4(hp + 4, v1.x * attn, v1.y * attn, v1.z * attn, v1.w * attn);
}

// ---------------- batchnorm -------------------------------------------------
__global__ void __launch_bounds__(256)
col_stats(const float* __restrict__ X, float* __restrict__ sum, float* __restrict__ sumsq)
{
    int col = blockIdx.x * 256 + threadIdx.x;   // gridDim.x = HID/256 = 2
    float s = 0.f, sq = 0.f;
    for (int r = blockIdx.y; r < NN; r += gridDim.y) {
        float x = X[(size_t)r * HID + col];
        s += x;
        sq = fmaf(x, x, sq);
    }
    atomicAdd(&sum[col], s);
    atomicAdd(&sumsq[col], sq);
}

__global__ void bn_finalize(const float* __restrict__ sum, const float* __restrict__ sumsq,
                            float* __restrict__ mu, float* __restrict__ rsig)
{
    int c = threadIdx.x + blockIdx.x * blockDim.x;
    if (c >= HID) return;
    float m = sum[c] * (1.f / NN);
    float var = sumsq[c] * (1.f / NN) - m * m;
    mu[c] = m;
    rsig[c] = rsqrtf(var + 1e-5f);
}

__global__ void bn_apply_sigmoid(float* __restrict__ X,
                                 const float* __restrict__ mu, const float* __restrict__ rsig,
                                 const float* __restrict__ g, const float* __restrict__ be)
{
    size_t i = (size_t)blockIdx.x * blockDim.x + threadIdx.x;
    if (i >= (size_t)NN * HID) return;
    int c = (int)(i & (HID - 1));
    float x = X[i];
    float y = (x - mu[c]) * rsig[c] * g[c] + be[c];
    X[i] = 1.f / (1.f + expf(-y));
}

// ---------------- fusion ----------------------------------------------------
__global__ void fuse_kernel(const float* __restrict__ alpha, const float* __restrict__ beta)
{
    size_t i = (size_t)blockIdx.x * blockDim.x + threadIdx.x;
    if (i >= (size_t)NN * HC) return;
    g_hg[i] = alpha[0] * g_hg[i] + beta[0] * g_hm[i];
}

// ---------------- launch ----------------------------------------------------
extern "C" void kernel_launch(void* const* d_in, const int* in_sizes, int n_in,
                              void* d_out, int out_size)
{
    const float* x_gsage = (const float*)d_in[0];
    const int*   ei      = (const int*)d_in[1];
    const float* x_mlp   = (const float*)d_in[2];
    const float* Wq = (const float*)d_in[3];  const float* bq = (const float*)d_in[4];
    const float* Wk = (const float*)d_in[5];  const float* bk = (const float*)d_in[6];
    const float* Wv = (const float*)d_in[7];  const float* bv = (const float*)d_in[8];
    const float* Ws = (const float*)d_in[9];  const float* bs = (const float*)d_in[10];
    const float* W1 = (const float*)d_in[11]; const float* b1 = (const float*)d_in[12];
    const float* g1 = (const float*)d_in[13]; const float* be1 = (const float*)d_in[14];
    const float* W2 = (const float*)d_in[15]; const float* b2 = (const float*)d_in[16];
    const float* g2 = (const float*)d_in[17]; const float* be2 = (const float*)d_in[18];
    const float* W3 = (const float*)d_in[19]; const float* b3 = (const float*)d_in[20];
    const float* alpha = (const float*)d_in[21];
    const float* beta  = (const float*)d_in[22];
    const float* Wc1 = (const float*)d_in[23]; const float* bc1 = (const float*)d_in[24];
    const float* Wc2 = (const float*)d_in[25]; const float* bc2 = (const float*)d_in[26];
    float* out = (float*)d_out;

    float *q, *k, *v, *hg, *hm, *h1, *h2;
    float *sum1, *sumsq1, *sum2, *sumsq2, *mu1, *rsig1, *mu2, *rsig2;
    cudaGetSymbolAddress((void**)&q,  g_q);
    cudaGetSymbolAddress((void**)&k,  g_k);
    cudaGetSymbolAddress((void**)&v,  g_v);
    cudaGetSymbolAddress((void**)&hg, g_hg);
    cudaGetSymbolAddress((void**)&hm, g_hm);
    cudaGetSymbolAddress((void**)&h1, g_h1);
    cudaGetSymbolAddress((void**)&h2, g_h2);
    cudaGetSymbolAddress((void**)&sum1, g_sum1);
    cudaGetSymbolAddress((void**)&sumsq1, g_sumsq1);
    cudaGetSymbolAddress((void**)&sum2, g_sum2);
    cudaGetSymbolAddress((void**)&sumsq2, g_sumsq2);
    cudaGetSymbolAddress((void**)&mu1, g_mu1);
    cudaGetSymbolAddress((void**)&rsig1, g_rsig1);
    cudaGetSymbolAddress((void**)&mu2, g_mu2);
    cudaGetSymbolAddress((void**)&rsig2, g_rsig2);

    dim3 blk(256);

    // init accumulators
    init_kernel<<<(NN * 2 + 255) / 256, blk>>>();

    const int MB = (NN + 127) / 128;   // 391

    // projections
    dim3 g256(HC / 128, MB);
    gemm_tf32<<<g256, blk>>>(x_gsage, Wq, bq, q,  NN, HC, GNN_IN, 0);
    gemm_tf32<<<g256, blk>>>(x_gsage, Wk, bk, k,  NN, HC, GNN_IN, 0);
    gemm_tf32<<<g256, blk>>>(x_gsage, Wv, bv, v,  NN, HC, GNN_IN, 0);
    gemm_tf32<<<g256, blk>>>(x_gsage, Ws, bs, hg, NN, HC, GNN_IN, 0);

    // attention
    edge_logits<<<(EE + 7) / 8, blk>>>(ei);
    decode_amax<<<(NN * 2 + 255) / 256, blk>>>();
    edge_exp<<<(EE * 2 + 255) / 256, blk>>>(ei);
    edge_aggregate<<<(EE + 7) / 8, blk>>>(ei);

    // MLP branch
    dim3 g512(HID / 128, MB);
    gemm_tf32<<<g512, blk>>>(x_mlp, W1, b1, h1, NN, HID, GNN_IN, 0);
    col_stats<<<dim3(HID / 256, 128), blk>>>(h1, sum1, sumsq1);
    bn_finalize<<<2, blk>>>(sum1, sumsq1, mu1, rsig1);
    bn_apply_sigmoid<<<((size_t)NN * HID + 255) / 256, blk>>>(h1, mu1, rsig1, g1, be1);

    gemm_tf32<<<g512, blk>>>(h1, W2, b2, h2, NN, HID, HID, 0);
    col_stats<<<dim3(HID / 256, 128), blk>>>(h2, sum2, sumsq2);
    bn_finalize<<<2, blk>>>(sum2, sumsq2, mu2, rsig2);
    bn_apply_sigmoid<<<((size_t)NN * HID + 255) / 256, blk>>>(h2, mu2, rsig2, g2, be2);

    gemm_tf32<<<g256, blk>>>(h2, W3, b3, hm, NN, HC, HID, 0);

    // fuse
    fuse_kernel<<<((size_t)NN * HC + 255) / 256, blk>>>(alpha, beta);

    // classifier head (reuse h1 as hidden)
    gemm_tf32<<<g512, blk>>>(hg, Wc1, bc1, h1, NN, HID, HC, 1);
    gemm_tf32<<<dim3(1, MB), blk>>>(h1, Wc2, bc2, out, NN, NCLS, HID, 0);
}

// round 3
// speedup vs baseline: 2.7023x; 1.2475x over previous
#include <cuda_runtime.h>
#include <math.h>
#include <stdint.h>

#define NN 50000
#define EE 800000
#define HID 512
#define HC 256
#define NCLS 40
#define QS 1024     // interleaved qkv+skip stride

// weight-buffer offsets (tf32-converted, row-major [N][K])
#define OFF_QKVS 0
#define OFF_W1   262144
#define OFF_W2   393216
#define OFF_W3   655360
#define OFF_WC1  786432
#define OFF_WC2  917504
#define WTF_TOT  937984

// ---------------- scratch ----------------------------------------------------
__device__ float g_qkvs[(size_t)NN * QS];   // cols: q[0,256) k[256,512) v[512,768) hg[768,1024)
__device__ float g_h1[(size_t)NN * HID];
__device__ float g_h2[(size_t)NN * HID];
__device__ float g_logit[(size_t)EE * 2];
__device__ float g_ex[(size_t)EE * 2];
__device__ unsigned g_amax[NN * 2];
__device__ float g_amaxf[NN * 2];
__device__ float g_denom[NN * 2];
__device__ float g_stats1[HID * 2];         // interleaved sum, sumsq
__device__ float g_stats2[HID * 2];
__device__ float g_mu1[HID], g_rsig1[HID], g_mu2[HID], g_rsig2[HID];
__device__ float g_wtf[WTF_TOT];
__device__ float g_bcat[QS];

// ---------------- helpers ----------------------------------------------------
__device__ __forceinline__ unsigned encF(float f) {
    unsigned u = __float_as_uint(f);
    return (u & 0x80000000u) ? ~u : (u | 0x80000000u);
}
__device__ __forceinline__ float decF(unsigned u) {
    return (u & 0x80000000u) ? __uint_as_float(u ^ 0x80000000u) : __uint_as_float(~u);
}
__device__ __forceinline__ void redAdd4(float* p, float a, float b, float c, float d) {
    asm volatile("red.global.add.v4.f32 [%0], {%1,%2,%3,%4};"
                 :: "l"(p), "f"(a), "f"(b), "f"(c), "f"(d) : "memory");
}
__device__ __forceinline__ unsigned f2tf(float f) {
    unsigned r;
    asm("cvt.rna.tf32.f32 %0, %1;" : "=r"(r) : "f"(f));
    return r;
}
__device__ __forceinline__ void ldsm4(unsigned& r0, unsigned& r1, unsigned& r2, unsigned& r3,
                                      unsigned addr) {
    asm volatile("ldmatrix.sync.aligned.m8n8.x4.shared.b16 {%0,%1,%2,%3}, [%4];"
                 : "=r"(r0), "=r"(r1), "=r"(r2), "=r"(r3) : "r"(addr));
}
__device__ __forceinline__ void mma8(float* d, const unsigned* a, const unsigned* b) {
    asm volatile("mma.sync.aligned.m16n8k8.row.col.f32.tf32.tf32.f32 "
                 "{%0,%1,%2,%3},{%4,%5,%6,%7},{%8,%9},{%0,%1,%2,%3};"
                 : "+f"(d[0]), "+f"(d[1]), "+f"(d[2]), "+f"(d[3])
                 : "r"(a[0]), "r"(a[1]), "r"(a[2]), "r"(a[3]), "r"(b[0]), "r"(b[1]));
}

// ---------------- preconvert weights to tf32 + concat biases -----------------
__global__ void preconv(const float* __restrict__ Wq, const float* __restrict__ Wk,
                        const float* __restrict__ Wv, const float* __restrict__ Ws,
                        const float* __restrict__ W1, const float* __restrict__ W2,
                        const float* __restrict__ W3, const float* __restrict__ Wc1,
                        const float* __restrict__ Wc2,
                        const float* __restrict__ bq, const float* __restrict__ bk,
                        const float* __restrict__ bv, const float* __restrict__ bs)
{
    int i = blockIdx.x * 256 + threadIdx.x;
    if (i < WTF_TOT) {
        float v;
        if (i < OFF_W1) {
            int wsel = i >> 16, idx = i & 65535;
            const float* src = (wsel == 0) ? Wq : (wsel == 1) ? Wk : (wsel == 2) ? Wv : Ws;
            v = src[idx];
        } else if (i < OFF_W2)  v = W1[i - OFF_W1];
        else if (i < OFF_W3)    v = W2[i - OFF_W2];
        else if (i < OFF_WC1)   v = W3[i - OFF_W3];
        else if (i < OFF_WC2)   v = Wc1[i - OFF_WC1];
        else                    v = Wc2[i - OFF_WC2];
        g_wtf[i] = __uint_as_float(f2tf(v));
    } else if (i < WTF_TOT + QS) {
        int j = i - WTF_TOT;
        int sel = j >> 8, idx = j & 255;
        const float* src = (sel == 0) ? bq : (sel == 1) ? bk : (sel == 2) ? bv : bs;
        g_bcat[j] = src[idx];
    }
}

// ---------------- init --------------------------------------------------------
__global__ void init_kernel() {
    int i = blockIdx.x * blockDim.x + threadIdx.x;
    if (i < NN * 2) {
        g_amax[i] = 0x007FFFFFu;
        g_denom[i] = 0.f;
    }
    if (i < HID * 2) {
        g_stats1[i] = 0.f;
        g_stats2[i] = 0.f;
    }
}

// ---------------- GEMM: C[M,N] = A[M,K] @ Btf[N,K]^T (+bias) ------------------
// Btf already tf32-rounded. 128x128 tile, BK=32, 2-stage pipeline,
// ldmatrix fragments, cp.async B, reg-staged A (cvt at STS).
// flags: 0=bias, 1=bias+relu, 2=no bias + column stats, 3=C=alpha*C+beta*(acc+bias)
__global__ void __launch_bounds__(256, 2)
gemm(const float* __restrict__ A, int lda,
     const float* __restrict__ Btf,
     const float* __restrict__ bias,
     float* __restrict__ C, int ldc,
     int M, int N, int K, int flags,
     float* __restrict__ stats,
     const float* __restrict__ alpha, const float* __restrict__ beta)
{
    extern __shared__ float sm[];
    const unsigned ASZ = 128 * 36 * 4;          // bytes per stage
    const unsigned B_OFF = 2 * ASZ;
    float* AsF = sm;
    unsigned s_base = (unsigned)__cvta_generic_to_shared(sm);

    const int tid = threadIdx.x, lane = tid & 31, w = tid >> 5;
    const int m0 = blockIdx.y * 128, n0 = blockIdx.x * 128;
    const int wm = (w & 3) * 32, wn = (w >> 2) * 64;
    const int g = lane >> 2, tg = lane & 3;
    const int cr = tid >> 3, cc = (tid & 7) * 4;
    const int mi4 = lane >> 3, rr = lane & 7;
    const unsigned frag_off = (((mi4 & 1) * 8 + rr) * 36 + (mi4 >> 1) * 4) * 4;

    float acc[2][8][4];
#pragma unroll
    for (int a = 0; a < 2; a++)
#pragma unroll
        for (int b = 0; b < 8; b++)
#pragma unroll
            for (int c = 0; c < 4; c++) acc[a][b][c] = 0.f;

    float4 ap[4];

    // ---- copy helpers (inlined manually via macros of loops) ----
#define LOAD_A(K0)                                                              \
    {                                                                           \
        _Pragma("unroll")                                                       \
        for (int t = 0; t < 4; t++) {                                           \
            int row = m0 + cr + t * 32;                                         \
            ap[t] = (row < M) ? *(const float4*)(A + (size_t)row * lda + (K0) + cc) \
                              : make_float4(0.f, 0.f, 0.f, 0.f);                \
        }                                                                       \
    }
#define STS_A(ST)                                                               \
    {                                                                           \
        _Pragma("unroll")                                                       \
        for (int t = 0; t < 4; t++) {                                           \
            uint4 u;                                                            \
            u.x = f2tf(ap[t].x); u.y = f2tf(ap[t].y);                           \
            u.z = f2tf(ap[t].z); u.w = f2tf(ap[t].w);                           \
            *(uint4*)(AsF + (ST) * 128 * 36 + (cr + t * 32) * 36 + cc) = u;     \
        }                                                                       \
    }
#define CP_B(K0, ST)                                                            \
    {                                                                           \
        _Pragma("unroll")                                                       \
        for (int t = 0; t < 4; t++) {                                           \
            int row = cr + t * 32;                                              \
            int nrow = n0 + row;                                                \
            int pred = (nrow < N) ? 16 : 0;                                     \
            int srow = (nrow < N) ? nrow : (N - 1);                             \
            unsigned dst = s_base + B_OFF + (ST) * ASZ + (row * 36 + cc) * 4;   \
            const float* src = Btf + (size_t)srow * K + (K0) + cc;              \
            asm volatile("cp.async.cg.shared.global [%0], [%1], 16, %2;"        \
                         :: "r"(dst), "l"(src), "r"(pred));                     \
        }                                                                       \
        asm volatile("cp.async.commit_group;");                                 \
    }

    // prologue
    LOAD_A(0);
    CP_B(0, 0);
    STS_A(0);
    asm volatile("cp.async.wait_group 0;");
    __syncthreads();

    const int T = K >> 5;
    for (int it = 0; it < T; ++it) {
        const int cur = it & 1, nxt = cur ^ 1;
        if (it + 1 < T) {
            LOAD_A((it + 1) * 32);
            CP_B((it + 1) * 32, nxt);
        }
        const unsigned aB = s_base + cur * ASZ + wm * 144 + frag_off;
        const unsigned bB = s_base + B_OFF + cur * ASZ + wn * 144 + frag_off;
#pragma unroll
        for (int ks = 0; ks < 4; ks++) {
            unsigned a0[4], a1[4], bf[8][2];
            ldsm4(a0[0], a0[1], a0[2], a0[3], aB + ks * 32);
            ldsm4(a1[0], a1[1], a1[2], a1[3], aB + 16 * 144 + ks * 32);
#pragma unroll
            for (int p = 0; p < 4; p++) {
                unsigned r0, r1, r2, r3;
                ldsm4(r0, r1, r2, r3, bB + p * 16 * 144 + ks * 32);
                bf[2 * p][0] = r0; bf[2 * p + 1][0] = r1;
                bf[2 * p][1] = r2; bf[2 * p + 1][1] = r3;
            }
#pragma unroll
            for (int nj = 0; nj < 8; nj++) {
                mma8(acc[0][nj], a0, bf[nj]);
                mma8(acc[1][nj], a1, bf[nj]);
            }
        }
        if (it + 1 < T) {
            STS_A(nxt);
            asm volatile("cp.async.wait_group 0;");
        }
        __syncthreads();
    }

    // ---- epilogue ----
    float alp = 0.f, bet = 0.f;
    if (flags == 3) { alp = alpha[0]; bet = beta[0]; }

#pragma unroll
    for (int mi = 0; mi < 2; mi++) {
        int r0 = m0 + wm + mi * 16 + g;
        int r1 = r0 + 8;
#pragma unroll
        for (int nj = 0; nj < 8; nj++) {
            int gc = n0 + wn + nj * 8 + 2 * tg;
            if (gc >= N) continue;
            float bx = 0.f, by = 0.f;
            if (flags != 2) { bx = bias[gc]; by = bias[gc + 1]; }
            float2 v0 = make_float2(acc[mi][nj][0] + bx, acc[mi][nj][1] + by);
            float2 v1 = make_float2(acc[mi][nj][2] + bx, acc[mi][nj][3] + by);
            if (flags == 1) {
                v0.x = fmaxf(v0.x, 0.f); v0.y = fmaxf(v0.y, 0.f);
                v1.x = fmaxf(v1.x, 0.f); v1.y = fmaxf(v1.y, 0.f);
            }
            if (flags == 3) {
                if (r0 < M) {
                    float2 o = *(float2*)(C + (size_t)r0 * ldc + gc);
                    v0.x = alp * o.x + bet * v0.x; v0.y = alp * o.y + bet * v0.y;
                }
                if (r1 < M) {
                    float2 o = *(float2*)(C + (size_t)r1 * ldc + gc);
                    v1.x = alp * o.x + bet * v1.x; v1.y = alp * o.y + bet * v1.y;
                }
            }
            if (r0 < M) *(float2*)(C + (size_t)r0 * ldc + gc) = v0;
            if (r1 < M) *(float2*)(C + (size_t)r1 * ldc + gc) = v1;
        }
    }

    if (flags == 2) {
#pragma unroll
        for (int nj = 0; nj < 8; nj++) {
            int gc = n0 + wn + nj * 8 + 2 * tg;
            float sx = acc[0][nj][0] + acc[0][nj][2] + acc[1][nj][0] + acc[1][nj][2];
            float sy = acc[0][nj][1] + acc[0][nj][3] + acc[1][nj][1] + acc[1][nj][3];
            float qx = acc[0][nj][0] * acc[0][nj][0] + acc[0][nj][2] * acc[0][nj][2]
                     + acc[1][nj][0] * acc[1][nj][0] + acc[1][nj][2] * acc[1][nj][2];
            float qy = acc[0][nj][1] * acc[0][nj][1] + acc[0][nj][3] * acc[0][nj][3]
                     + acc[1][nj][1] * acc[1][nj][1] + acc[1][nj][3] * acc[1][nj][3];
#pragma unroll
            for (int o = 4; o < 32; o <<= 1) {
                sx += __shfl_xor_sync(0xFFFFFFFFu, sx, o);
                sy += __shfl_xor_sync(0xFFFFFFFFu, sy, o);
                qx += __shfl_xor_sync(0xFFFFFFFFu, qx, o);
                qy += __shfl_xor_sync(0xFFFFFFFFu, qy, o);
            }
            if (lane < 4) redAdd4(&stats[gc * 2], sx, qx, sy, qy);
        }
    }
#undef LOAD_A
#undef STS_A
#undef CP_B
}

// ---------------- edge kernels ------------------------------------------------
__global__ void __launch_bounds__(256)
edge_logits(const int* __restrict__ ei)
{
    int e = blockIdx.x * 8 + (threadIdx.x >> 5);
    if (e >= EE) return;
    int lane = threadIdx.x & 31;
    int src = ei[e];
    int dst = ei[EE + e];
#pragma unroll
    for (int h = 0; h < 2; h++) {
        float4 qv = *(const float4*)(g_qkvs + (size_t)dst * QS + h * 128 + lane * 4);
        float4 kv = *(const float4*)(g_qkvs + (size_t)src * QS + 256 + h * 128 + lane * 4);
        float d = qv.x * kv.x + qv.y * kv.y + qv.z * kv.z + qv.w * kv.w;
#pragma unroll
        for (int off = 16; off; off >>= 1) d += __shfl_xor_sync(0xFFFFFFFFu, d, off);
        d *= 0.08838834764831845f;
        if (lane == 0) {
            g_logit[(size_t)e * 2 + h] = d;
            atomicMax(&g_amax[(size_t)dst * 2 + h], encF(d));
        }
    }
}

__global__ void decode_amax() {
    int i = blockIdx.x * blockDim.x + threadIdx.x;
    if (i >= NN * 2) return;
    float d = decF(g_amax[i]);
    g_amaxf[i] = isfinite(d) ? d : 0.f;
}

__global__ void edge_exp(const int* __restrict__ ei) {
    int idx = blockIdx.x * blockDim.x + threadIdx.x;
    if (idx >= EE * 2) return;
    int e = idx >> 1, h = idx & 1;
    int dst = ei[EE + e];
    float ex = expf(g_logit[idx] - g_amaxf[(size_t)dst * 2 + h]);
    g_ex[idx] = ex;
    atomicAdd(&g_denom[(size_t)dst * 2 + h], ex);
}

__global__ void __launch_bounds__(256)
edge_aggregate(const int* __restrict__ ei)
{
    int e = blockIdx.x * 8 + (threadIdx.x >> 5);
    if (e >= EE) return;
    int lane = threadIdx.x & 31;
    int src = ei[e];
    int dst = ei[EE + e];
    int h = lane >> 4;
    int c = (lane & 15) * 8;
    float attn = g_ex[(size_t)e * 2 + h] /
                 fmaxf(g_denom[(size_t)dst * 2 + h], 1e-16f);
    const float4* vp = (const float4*)(g_qkvs + (size_t)src * QS + 512 + h * 128 + c);
    float* hp = g_qkvs + (size_t)dst * QS + 768 + h * 128 + c;
    float4 v0 = vp[0], v1 = vp[1];
    redAdd4(hp,     v0.x * attn, v0.y * attn, v0.z * attn, v0.w * attn);
    redAdd4(hp + 4, v1.x * attn, v1.y * attn, v1.z * attn, v1.w * attn);
}

// ---------------- batchnorm ----------------------------------------------------
__global__ void bn_finalize(const float* __restrict__ stats,
                            float* __restrict__ mu, float* __restrict__ rsig)
{
    int c = threadIdx.x + blockIdx.x * blockDim.x;
    if (c >= HID) return;
    float m = stats[c * 2] * (1.f / NN);
    float var = stats[c * 2 + 1] * (1.f / NN) - m * m;
    mu[c] = m;
    rsig[c] = rsqrtf(var + 1e-5f);
}

__global__ void bn_apply_sigmoid(float* __restrict__ X,
                                 const float* __restrict__ mu, const float* __restrict__ rsig,
                                 const float* __restrict__ g, const float* __restrict__ be)
{
    size_t i = (size_t)blockIdx.x * blockDim.x + threadIdx.x;
    if (i >= (size_t)NN * HID) return;
    int c = (int)(i & (HID - 1));
    float x = X[i];
    float y = (x - mu[c]) * rsig[c] * g[c] + be[c];
    X[i] = 1.f / (1.f + expf(-y));
}

// ---------------- launch --------------------------------------------------------
extern "C" void kernel_launch(void* const* d_in, const int* in_sizes, int n_in,
                              void* d_out, int out_size)
{
    const float* x_gsage = (const float*)d_in[0];
    const int*   ei      = (const int*)d_in[1];
    const float* x_mlp   = (const float*)d_in[2];
    const float* Wq = (const float*)d_in[3];  const float* bq = (const float*)d_in[4];
    const float* Wk = (const float*)d_in[5];  const float* bk = (const float*)d_in[6];
    const float* Wv = (const float*)d_in[7];  const float* bv = (const float*)d_in[8];
    const float* Ws = (const float*)d_in[9];  const float* bs = (const float*)d_in[10];
    const float* W1 = (const float*)d_in[11];
    const float* g1 = (const float*)d_in[13]; const float* be1 = (const float*)d_in[14];
    const float* W2 = (const float*)d_in[15];
    const float* g2 = (const float*)d_in[17]; const float* be2 = (const float*)d_in[18];
    const float* W3 = (const float*)d_in[19]; const float* b3 = (const float*)d_in[20];
    const float* alpha = (const float*)d_in[21];
    const float* beta  = (const float*)d_in[22];
    const float* Wc1 = (const float*)d_in[23]; const float* bc1 = (const float*)d_in[24];
    const float* Wc2 = (const float*)d_in[25]; const float* bc2 = (const float*)d_in[26];
    float* out = (float*)d_out;

    float *qkvs, *h1, *h2, *wtf, *bcat;
    float *stats1, *stats2, *mu1, *rsig1, *mu2, *rsig2;
    cudaGetSymbolAddress((void**)&qkvs, g_qkvs);
    cudaGetSymbolAddress((void**)&h1, g_h1);
    cudaGetSymbolAddress((void**)&h2, g_h2);
    cudaGetSymbolAddress((void**)&wtf, g_wtf);
    cudaGetSymbolAddress((void**)&bcat, g_bcat);
    cudaGetSymbolAddress((void**)&stats1, g_stats1);
    cudaGetSymbolAddress((void**)&stats2, g_stats2);
    cudaGetSymbolAddress((void**)&mu1, g_mu1);
    cudaGetSymbolAddress((void**)&rsig1, g_rsig1);
    cudaGetSymbolAddress((void**)&mu2, g_mu2);
    cudaGetSymbolAddress((void**)&rsig2, g_rsig2);

    static bool attr_set = false;
    if (!attr_set) {
        cudaFuncSetAttribute(gemm, cudaFuncAttributeMaxDynamicSharedMemorySize, 73728);
        attr_set = true;
    }
    const int SMB = 73728;
    const int MB = (NN + 127) / 128;
    dim3 blk(256);

    preconv<<<(WTF_TOT + QS + 255) / 256, blk>>>(Wq, Wk, Wv, Ws, W1, W2, W3, Wc1, Wc2,
                                                 bq, bk, bv, bs);
    init_kernel<<<(NN * 2 + 255) / 256, blk>>>();

    // fused q|k|v|skip projection (N=1024)
    gemm<<<dim3(8, MB), blk, SMB>>>(x_gsage, 256, wtf + OFF_QKVS, bcat, qkvs, QS,
                                    NN, 1024, 256, 0, nullptr, nullptr, nullptr);

    // attention
    edge_logits<<<(EE + 7) / 8, blk>>>(ei);
    decode_amax<<<(NN * 2 + 255) / 256, blk>>>();
    edge_exp<<<(EE * 2 + 255) / 256, blk>>>(ei);
    edge_aggregate<<<(EE + 7) / 8, blk>>>(ei);

    // MLP branch (bias cancels through BN -> flags=2 = no bias + fused stats)
    gemm<<<dim3(4, MB), blk, SMB>>>(x_mlp, 256, wtf + OFF_W1, nullptr, h1, HID,
                                    NN, HID, 256, 2, stats1, nullptr, nullptr);
    bn_finalize<<<2, blk>>>(stats1, mu1, rsig1);
    bn_apply_sigmoid<<<((size_t)NN * HID + 255) / 256, blk>>>(h1, mu1, rsig1, g1, be1);

    gemm<<<dim3(4, MB), blk, SMB>>>(h1, HID, wtf + OFF_W2, nullptr, h2, HID,
                                    NN, HID, HID, 2, stats2, nullptr, nullptr);
    bn_finalize<<<2, blk>>>(stats2, mu2, rsig2);
    bn_apply_sigmoid<<<((size_t)NN * HID + 255) / 256, blk>>>(h2, mu2, rsig2, g2, be2);

    // W3 with fused alpha/beta combine, in place into hg region of qkvs
    gemm<<<dim3(2, MB), blk, SMB>>>(h2, HID, wtf + OFF_W3, b3, qkvs + 768, QS,
                                    NN, HC, HID, 3, nullptr, alpha, beta);

    // classifier
    gemm<<<dim3(4, MB), blk, SMB>>>(qkvs + 768, QS, wtf + OFF_WC1, bc1, h1, HID,
                                    NN, HID, HC, 1, nullptr, nullptr, nullptr);
    gemm<<<dim3(1, MB), blk, SMB>>>(h1, HID, wtf + OFF_WC2, bc2, out, NCLS,
                                    NN, NCLS, HID, 0, nullptr, nullptr, nullptr);
}

// round 4
// speedup vs baseline: 3.1275x; 1.1573x over previous
#include <cuda_runtime.h>
#include <math.h>
#include <stdint.h>

#define NN 50000
#define EE 800000
#define HID 512
#define HC 256
#define NCLS 40
#define QS 1024     // interleaved qkv+skip stride

// weight-buffer offsets (tf32-converted, row-major [N][K])
#define OFF_QKVS 0
#define OFF_W1   262144
#define OFF_W2   393216
#define OFF_W3   655360
#define OFF_WC1  786432
#define OFF_WC2  917504
#define WTF_TOT  937984

// ---------------- scratch ----------------------------------------------------
__device__ float g_qkvs[(size_t)NN * QS];   // cols: q[0,256) k[256,512) v[512,768) hg[768,1024)
__device__ float g_h1[(size_t)NN * HID];
__device__ float g_h2[(size_t)NN * HID];
__device__ int   g_deg[NN];
__device__ int   g_off[NN + 1];
__device__ int   g_cursor[NN];
__device__ int   g_csr_src[EE];
__device__ float g_stats1[HID * 2];         // interleaved sum, sumsq
__device__ float g_stats2[HID * 2];
__device__ float g_mu1[HID], g_rsig1[HID], g_mu2[HID], g_rsig2[HID];
__device__ float g_wtf[WTF_TOT];
__device__ float g_bcat[QS];

// ---------------- helpers ----------------------------------------------------
__device__ __forceinline__ void redAdd4(float* p, float a, float b, float c, float d) {
    asm volatile("red.global.add.v4.f32 [%0], {%1,%2,%3,%4};"
                 :: "l"(p), "f"(a), "f"(b), "f"(c), "f"(d) : "memory");
}
__device__ __forceinline__ unsigned f2tf(float f) {
    unsigned r;
    asm("cvt.rna.tf32.f32 %0, %1;" : "=r"(r) : "f"(f));
    return r;
}
__device__ __forceinline__ void ldsm4(unsigned& r0, unsigned& r1, unsigned& r2, unsigned& r3,
                                      unsigned addr) {
    asm volatile("ldmatrix.sync.aligned.m8n8.x4.shared.b16 {%0,%1,%2,%3}, [%4];"
                 : "=r"(r0), "=r"(r1), "=r"(r2), "=r"(r3) : "r"(addr));
}
__device__ __forceinline__ void mma8(float* d, const unsigned* a, const unsigned* b) {
    asm volatile("mma.sync.aligned.m16n8k8.row.col.f32.tf32.tf32.f32 "
                 "{%0,%1,%2,%3},{%4,%5,%6,%7},{%8,%9},{%0,%1,%2,%3};"
                 : "+f"(d[0]), "+f"(d[1]), "+f"(d[2]), "+f"(d[3])
                 : "r"(a[0]), "r"(a[1]), "r"(a[2]), "r"(a[3]), "r"(b[0]), "r"(b[1]));
}

// ---------------- preconvert weights to tf32 + concat biases -----------------
__global__ void preconv(const float* __restrict__ Wq, const float* __restrict__ Wk,
                        const float* __restrict__ Wv, const float* __restrict__ Ws,
                        const float* __restrict__ W1, const float* __restrict__ W2,
                        const float* __restrict__ W3, const float* __restrict__ Wc1,
                        const float* __restrict__ Wc2,
                        const float* __restrict__ bq, const float* __restrict__ bk,
                        const float* __restrict__ bv, const float* __restrict__ bs)
{
    int i = blockIdx.x * 256 + threadIdx.x;
    if (i < WTF_TOT) {
        float v;
        if (i < OFF_W1) {
            int wsel = i >> 16, idx = i & 65535;
            const float* src = (wsel == 0) ? Wq : (wsel == 1) ? Wk : (wsel == 2) ? Wv : Ws;
            v = src[idx];
        } else if (i < OFF_W2)  v = W1[i - OFF_W1];
        else if (i < OFF_W3)    v = W2[i - OFF_W2];
        else if (i < OFF_WC1)   v = W3[i - OFF_W3];
        else if (i < OFF_WC2)   v = Wc1[i - OFF_WC1];
        else                    v = Wc2[i - OFF_WC2];
        g_wtf[i] = __uint_as_float(f2tf(v));
    } else if (i < WTF_TOT + QS) {
        int j = i - WTF_TOT;
        int sel = j >> 8, idx = j & 255;
        const float* src = (sel == 0) ? bq : (sel == 1) ? bk : (sel == 2) ? bv : bs;
        g_bcat[j] = src[idx];
    }
}

// ---------------- init --------------------------------------------------------
__global__ void init_kernel() {
    int i = blockIdx.x * blockDim.x + threadIdx.x;
    if (i < NN) g_deg[i] = 0;
    if (i < HID * 2) {
        g_stats1[i] = 0.f;
        g_stats2[i] = 0.f;
    }
}

// ---------------- CSR build ----------------------------------------------------
__global__ void count_deg(const int* __restrict__ ei) {
    int e = blockIdx.x * blockDim.x + threadIdx.x;
    if (e >= EE) return;
    atomicAdd(&g_deg[ei[EE + e]], 1);
}

// single-block inclusive scan over degrees -> offsets
__global__ void __launch_bounds__(1024)
scan_offsets() {
    __shared__ int sm[1024];
    __shared__ int carry;
    if (threadIdx.x == 0) carry = 0;
    __syncthreads();
    for (int base = 0; base < NN; base += 1024) {
        int i = base + threadIdx.x;
        int v = (i < NN) ? g_deg[i] : 0;
        sm[threadIdx.x] = v;
        __syncthreads();
#pragma unroll
        for (int s = 1; s < 1024; s <<= 1) {
            int t = (threadIdx.x >= s) ? sm[threadIdx.x - s] : 0;
            __syncthreads();
            sm[threadIdx.x] += t;
            __syncthreads();
        }
        if (i < NN) {
            int off = carry + sm[threadIdx.x];
            g_off[i + 1] = off;
            g_cursor[i] = off - v;   // exclusive prefix = start cursor
        }
        __syncthreads();
        if (threadIdx.x == 1023) carry += sm[1023];
        __syncthreads();
    }
    if (threadIdx.x == 0) g_off[0] = 0;
}

__global__ void scatter_edges(const int* __restrict__ ei) {
    int e = blockIdx.x * blockDim.x + threadIdx.x;
    if (e >= EE) return;
    int src = ei[e];
    int dst = ei[EE + e];
    int pos = atomicAdd(&g_cursor[dst], 1);
    g_csr_src[pos] = src;
}

// ---------------- fused attention: warp per (dst, head), online softmax --------
__global__ void __launch_bounds__(256)
attn_fused()
{
    int widx = blockIdx.x * 8 + (threadIdx.x >> 5);
    if (widx >= NN * 2) return;
    int nid = widx >> 1;
    int h = widx & 1;
    int lane = threadIdx.x & 31;

    float4 q4 = *(const float4*)(g_qkvs + (size_t)nid * QS + h * 128 + lane * 4);
    q4.x *= 0.08838834764831845f; q4.y *= 0.08838834764831845f;
    q4.z *= 0.08838834764831845f; q4.w *= 0.08838834764831845f;

    int beg = g_off[nid], end = g_off[nid + 1];
    if (beg == end) return;   // no incoming edges: hg keeps skip only

    float m = -1e30f, d = 0.f;
    float ax = 0.f, ay = 0.f, az = 0.f, aw = 0.f;

    for (int j = beg; j < end; j++) {
        int src = g_csr_src[j];
        const float* kp = g_qkvs + (size_t)src * QS + 256 + h * 128 + lane * 4;
        float4 k4 = *(const float4*)kp;
        float4 v4 = *(const float4*)(kp + 256);   // v block is +256 floats after k
        float l = q4.x * k4.x + q4.y * k4.y + q4.z * k4.z + q4.w * k4.w;
#pragma unroll
        for (int o = 16; o; o >>= 1) l += __shfl_xor_sync(0xFFFFFFFFu, l, o);
        if (l > m) {
            float s = __expf(m - l);
            d = d * s + 1.f;
            ax = ax * s + v4.x; ay = ay * s + v4.y;
            az = az * s + v4.z; aw = aw * s + v4.w;
            m = l;
        } else {
            float w = __expf(l - m);
            d += w;
            ax += w * v4.x; ay += w * v4.y;
            az += w * v4.z; aw += w * v4.w;
        }
    }

    float inv = 1.f / fmaxf(d, 1e-16f);
    float* op = g_qkvs + (size_t)nid * QS + 768 + h * 128 + lane * 4;
    float4 o = *(const float4*)op;    // skip projection
    o.x += ax * inv; o.y += ay * inv; o.z += az * inv; o.w += aw * inv;
    *(float4*)op = o;
}

// ---------------- GEMM: C[M,N] = A[M,K] @ Btf[N,K]^T (+bias) ------------------
// flags: 0=bias, 1=bias+relu, 2=no bias + column stats, 3=C=alpha*C+beta*(acc+bias)
__global__ void __launch_bounds__(256, 2)
gemm(const float* __restrict__ A, int lda,
     const float* __restrict__ Btf,
     const float* __restrict__ bias,
     float* __restrict__ C, int ldc,
     int M, int N, int K, int flags,
     float* __restrict__ stats,
     const float* __restrict__ alpha, const float* __restrict__ beta)
{
    extern __shared__ float sm[];
    const unsigned ASZ = 128 * 36 * 4;          // bytes per stage
    const unsigned B_OFF = 2 * ASZ;
    float* AsF = sm;
    unsigned s_base = (unsigned)__cvta_generic_to_shared(sm);

    const int tid = threadIdx.x, lane = tid & 31, w = tid >> 5;
    const int m0 = blockIdx.y * 128, n0 = blockIdx.x * 128;
    const int wm = (w & 3) * 32, wn = (w >> 2) * 64;
    const int g = lane >> 2, tg = lane & 3;
    const int cr = tid >> 3, cc = (tid & 7) * 4;
    const int mi4 = lane >> 3, rr = lane & 7;
    const unsigned frag_off = (((mi4 & 1) * 8 + rr) * 36 + (mi4 >> 1) * 4) * 4;

    float acc[2][8][4];
#pragma unroll
    for (int a = 0; a < 2; a++)
#pragma unroll
        for (int b = 0; b < 8; b++)
#pragma unroll
            for (int c = 0; c < 4; c++) acc[a][b][c] = 0.f;

    float4 ap[4];

#define LOAD_A(K0)                                                              \
    {                                                                           \
        _Pragma("unroll")                                                       \
        for (int t = 0; t < 4; t++) {                                           \
            int row = m0 + cr + t * 32;                                         \
            ap[t] = (row < M) ? *(const float4*)(A + (size_t)row * lda + (K0) + cc) \
                              : make_float4(0.f, 0.f, 0.f, 0.f);                \
        }                                                                       \
    }
#define STS_A(ST)                                                               \
    {                                                                           \
        _Pragma("unroll")                                                       \
        for (int t = 0; t < 4; t++) {                                           \
            uint4 u;                                                            \
            u.x = f2tf(ap[t].x); u.y = f2tf(ap[t].y);                           \
            u.z = f2tf(ap[t].z); u.w = f2tf(ap[t].w);                           \
            *(uint4*)(AsF + (ST) * 128 * 36 + (cr + t * 32) * 36 + cc) = u;     \
        }                                                                       \
    }
#define CP_B(K0, ST)                                                            \
    {                                                                           \
        _Pragma("unroll")                                                       \
        for (int t = 0; t < 4; t++) {                                           \
            int row = cr + t * 32;                                              \
            int nrow = n0 + row;                                                \
            int pred = (nrow < N) ? 16 : 0;                                     \
            int srow = (nrow < N) ? nrow : (N - 1);                             \
            unsigned dst = s_base + B_OFF + (ST) * ASZ + (row * 36 + cc) * 4;   \
            const float* src = Btf + (size_t)srow * K + (K0) + cc;              \
            asm volatile("cp.async.cg.shared.global [%0], [%1], 16, %2;"        \
                         :: "r"(dst), "l"(src), "r"(pred));                     \
        }                                                                       \
        asm volatile("cp.async.commit_group;");                                 \
    }

    LOAD_A(0);
    CP_B(0, 0);
    STS_A(0);
    asm volatile("cp.async.wait_group 0;");
    __syncthreads();

    const int T = K >> 5;
    for (int it = 0; it < T; ++it) {
        const int cur = it & 1, nxt = cur ^ 1;
        if (it + 1 < T) {
            LOAD_A((it + 1) * 32);
            CP_B((it + 1) * 32, nxt);
        }
        const unsigned aB = s_base + cur * ASZ + wm * 144 + frag_off;
        const unsigned bB = s_base + B_OFF + cur * ASZ + wn * 144 + frag_off;
#pragma unroll
        for (int ks = 0; ks < 4; ks++) {
            unsigned a0[4], a1[4], bf[8][2];
            ldsm4(a0[0], a0[1], a0[2], a0[3], aB + ks * 32);
            ldsm4(a1[0], a1[1], a1[2], a1[3], aB + 16 * 144 + ks * 32);
#pragma unroll
            for (int p = 0; p < 4; p++) {
                unsigned r0, r1, r2, r3;
                ldsm4(r0, r1, r2, r3, bB + p * 16 * 144 + ks * 32);
                bf[2 * p][0] = r0; bf[2 * p + 1][0] = r1;
                bf[2 * p][1] = r2; bf[2 * p + 1][1] = r3;
            }
#pragma unroll
            for (int nj = 0; nj < 8; nj++) {
                mma8(acc[0][nj], a0, bf[nj]);
                mma8(acc[1][nj], a1, bf[nj]);
            }
        }
        if (it + 1 < T) {
            STS_A(nxt);
            asm volatile("cp.async.wait_group 0;");
        }
        __syncthreads();
    }

    float alp = 0.f, bet = 0.f;
    if (flags == 3) { alp = alpha[0]; bet = beta[0]; }

#pragma unroll
    for (int mi = 0; mi < 2; mi++) {
        int r0 = m0 + wm + mi * 16 + g;
        int r1 = r0 + 8;
#pragma unroll
        for (int nj = 0; nj < 8; nj++) {
            int gc = n0 + wn + nj * 8 + 2 * tg;
            if (gc >= N) continue;
            float bx = 0.f, by = 0.f;
            if (flags != 2) { bx = bias[gc]; by = bias[gc + 1]; }
            float2 v0 = make_float2(acc[mi][nj][0] + bx, acc[mi][nj][1] + by);
            float2 v1 = make_float2(acc[mi][nj][2] + bx, acc[mi][nj][3] + by);
            if (flags == 1) {
                v0.x = fmaxf(v0.x, 0.f); v0.y = fmaxf(v0.y, 0.f);
                v1.x = fmaxf(v1.x, 0.f); v1.y = fmaxf(v1.y, 0.f);
            }
            if (flags == 3) {
                if (r0 < M) {
                    float2 o = *(float2*)(C + (size_t)r0 * ldc + gc);
                    v0.x = alp * o.x + bet * v0.x; v0.y = alp * o.y + bet * v0.y;
                }
                if (r1 < M) {
                    float2 o = *(float2*)(C + (size_t)r1 * ldc + gc);
                    v1.x = alp * o.x + bet * v1.x; v1.y = alp * o.y + bet * v1.y;
                }
            }
            if (r0 < M) *(float2*)(C + (size_t)r0 * ldc + gc) = v0;
            if (r1 < M) *(float2*)(C + (size_t)r1 * ldc + gc) = v1;
        }
    }

    if (flags == 2) {
#pragma unroll
        for (int nj = 0; nj < 8; nj++) {
            int gc = n0 + wn + nj * 8 + 2 * tg;
            float sx = acc[0][nj][0] + acc[0][nj][2] + acc[1][nj][0] + acc[1][nj][2];
            float sy = acc[0][nj][1] + acc[0][nj][3] + acc[1][nj][1] + acc[1][nj][3];
            float qx = acc[0][nj][0] * acc[0][nj][0] + acc[0][nj][2] * acc[0][nj][2]
                     + acc[1][nj][0] * acc[1][nj][0] + acc[1][nj][2] * acc[1][nj][2];
            float qy = acc[0][nj][1] * acc[0][nj][1] + acc[0][nj][3] * acc[0][nj][3]
                     + acc[1][nj][1] * acc[1][nj][1] + acc[1][nj][3] * acc[1][nj][3];
#pragma unroll
            for (int o = 4; o < 32; o <<= 1) {
                sx += __shfl_xor_sync(0xFFFFFFFFu, sx, o);
                sy += __shfl_xor_sync(0xFFFFFFFFu, sy, o);
                qx += __shfl_xor_sync(0xFFFFFFFFu, qx, o);
                qy += __shfl_xor_sync(0xFFFFFFFFu, qy, o);
            }
            if (lane < 4) redAdd4(&stats[gc * 2], sx, qx, sy, qy);
        }
    }
#undef LOAD_A
#undef STS_A
#undef CP_B
}

// ---------------- batchnorm ----------------------------------------------------
__global__ void bn_finalize(const float* __restrict__ stats,
                            float* __restrict__ mu, float* __restrict__ rsig)
{
    int c = threadIdx.x + blockIdx.x * blockDim.x;
    if (c >= HID) return;
    float m = stats[c * 2] * (1.f / NN);
    float var = stats[c * 2 + 1] * (1.f / NN) - m * m;
    mu[c] = m;
    rsig[c] = rsqrtf(var + 1e-5f);
}

__global__ void bn_apply_sigmoid(float* __restrict__ X,
                                 const float* __restrict__ mu, const float* __restrict__ rsig,
                                 const float* __restrict__ g, const float* __restrict__ be)
{
    size_t i = (size_t)blockIdx.x * blockDim.x + threadIdx.x;
    if (i >= (size_t)NN * HID) return;
    int c = (int)(i & (HID - 1));
    float x = X[i];
    float y = (x - mu[c]) * rsig[c] * g[c] + be[c];
    X[i] = 1.f / (1.f + expf(-y));
}

// ---------------- launch --------------------------------------------------------
extern "C" void kernel_launch(void* const* d_in, const int* in_sizes, int n_in,
                              void* d_out, int out_size)
{
    const float* x_gsage = (const float*)d_in[0];
    const int*   ei      = (const int*)d_in[1];
    const float* x_mlp   = (const float*)d_in[2];
    const float* Wq = (const float*)d_in[3];  const float* bq = (const float*)d_in[4];
    const float* Wk = (const float*)d_in[5];  const float* bk = (const float*)d_in[6];
    const float* Wv = (const float*)d_in[7];  const float* bv = (const float*)d_in[8];
    const float* Ws = (const float*)d_in[9];  const float* bs = (const float*)d_in[10];
    const float* W1 = (const float*)d_in[11];
    const float* g1 = (const float*)d_in[13]; const float* be1 = (const float*)d_in[14];
    const float* W2 = (const float*)d_in[15];
    const float* g2 = (const float*)d_in[17]; const float* be2 = (const float*)d_in[18];
    const float* W3 = (const float*)d_in[19]; const float* b3 = (const float*)d_in[20];
    const float* alpha = (const float*)d_in[21];
    const float* beta  = (const float*)d_in[22];
    const float* Wc1 = (const float*)d_in[23]; const float* bc1 = (const float*)d_in[24];
    const float* Wc2 = (const float*)d_in[25]; const float* bc2 = (const float*)d_in[26];
    float* out = (float*)d_out;

    float *qkvs, *h1, *h2, *wtf, *bcat;
    float *stats1, *stats2, *mu1, *rsig1, *mu2, *rsig2;
    cudaGetSymbolAddress((void**)&qkvs, g_qkvs);
    cudaGetSymbolAddress((void**)&h1, g_h1);
    cudaGetSymbolAddress((void**)&h2, g_h2);
    cudaGetSymbolAddress((void**)&wtf, g_wtf);
    cudaGetSymbolAddress((void**)&bcat, g_bcat);
    cudaGetSymbolAddress((void**)&stats1, g_stats1);
    cudaGetSymbolAddress((void**)&stats2, g_stats2);
    cudaGetSymbolAddress((void**)&mu1, g_mu1);
    cudaGetSymbolAddress((void**)&rsig1, g_rsig1);
    cudaGetSymbolAddress((void**)&mu2, g_mu2);
    cudaGetSymbolAddress((void**)&rsig2, g_rsig2);

    static bool attr_set = false;
    if (!attr_set) {
        cudaFuncSetAttribute(gemm, cudaFuncAttributeMaxDynamicSharedMemorySize, 73728);
        attr_set = true;
    }
    const int SMB = 73728;
    const int MB = (NN + 127) / 128;
    dim3 blk(256);

    preconv<<<(WTF_TOT + QS + 255) / 256, blk>>>(Wq, Wk, Wv, Ws, W1, W2, W3, Wc1, Wc2,
                                                 bq, bk, bv, bs);
    init_kernel<<<(NN + 255) / 256, blk>>>();

    // CSR build (independent of projections)
    count_deg<<<(EE + 255) / 256, blk>>>(ei);
    scan_offsets<<<1, 1024>>>();
    scatter_edges<<<(EE + 255) / 256, blk>>>(ei);

    // fused q|k|v|skip projection (N=1024)
    gemm<<<dim3(8, MB), blk, SMB>>>(x_gsage, 256, wtf + OFF_QKVS, bcat, qkvs, QS,
                                    NN, 1024, 256, 0, nullptr, nullptr, nullptr);

    // fused attention (online softmax, no atomics)
    attn_fused<<<(NN * 2 + 7) / 8, blk>>>();

    // MLP branch (bias cancels through BN -> flags=2 = no bias + fused stats)
    gemm<<<dim3(4, MB), blk, SMB>>>(x_mlp, 256, wtf + OFF_W1, nullptr, h1, HID,
                                    NN, HID, 256, 2, stats1, nullptr, nullptr);
    bn_finalize<<<2, blk>>>(stats1, mu1, rsig1);
    bn_apply_sigmoid<<<((size_t)NN * HID + 255) / 256, blk>>>(h1, mu1, rsig1, g1, be1);

    gemm<<<dim3(4, MB), blk, SMB>>>(h1, HID, wtf + OFF_W2, nullptr, h2, HID,
                                    NN, HID, HID, 2, stats2, nullptr, nullptr);
    bn_finalize<<<2, blk>>>(stats2, mu2, rsig2);
    bn_apply_sigmoid<<<((size_t)NN * HID + 255) / 256, blk>>>(h2, mu2, rsig2, g2, be2);

    // W3 with fused alpha/beta combine, in place into hg region of qkvs
    gemm<<<dim3(2, MB), blk, SMB>>>(h2, HID, wtf + OFF_W3, b3, qkvs + 768, QS,
                                    NN, HC, HID, 3, nullptr, alpha, beta);

    // classifier
    gemm<<<dim3(4, MB), blk, SMB>>>(qkvs + 768, QS, wtf + OFF_WC1, bc1, h1, HID,
                                    NN, HID, HC, 1, nullptr, nullptr, nullptr);
    gemm<<<dim3(1, MB), blk, SMB>>>(h1, HID, wtf + OFF_WC2, bc2, out, NCLS,
                                    NN, NCLS, HID, 0, nullptr, nullptr, nullptr);
}

// round 5
// speedup vs baseline: 3.2834x; 1.0498x over previous
#include <cuda_runtime.h>
#include <math.h>
#include <stdint.h>

#define NN 50000
#define EE 800000
#define HID 512
#define HC 256
#define NCLS 40
#define QS 1024     // interleaved qkv+skip stride
#define NBLK 196    // ceil(NN/256)

// weight-buffer offsets (tf32-converted, row-major [N][K])
#define OFF_QKVS 0
#define OFF_W1   262144
#define OFF_W2   393216
#define OFF_W3   655360
#define OFF_WC1  786432
#define OFF_WC2  917504
#define WTF_TOT  937984

// ---------------- scratch ----------------------------------------------------
__device__ float g_qkvs[(size_t)NN * QS];   // q[0,256) k[256,512) v[512,768) hg[768,1024)
__device__ float g_h1[(size_t)NN * HID];
__device__ float g_h2[(size_t)NN * HID];
__device__ int   g_deg[NN];
__device__ int   g_off[NN + 1];
__device__ int   g_cursor[NN];
__device__ int   g_csr_src[EE];
__device__ int   g_bsum[256];
__device__ int   g_bpref[256];
__device__ float g_stats1[HID * 2];         // interleaved sum, sumsq
__device__ float g_stats2[HID * 2];
__device__ float g_mu1[HID], g_rsig1[HID], g_mu2[HID], g_rsig2[HID];
__device__ float g_wtf[WTF_TOT];
__device__ float g_bcat[QS];

// ---------------- helpers ----------------------------------------------------
__device__ __forceinline__ void redAdd4(float* p, float a, float b, float c, float d) {
    asm volatile("red.global.add.v4.f32 [%0], {%1,%2,%3,%4};"
                 :: "l"(p), "f"(a), "f"(b), "f"(c), "f"(d) : "memory");
}
__device__ __forceinline__ unsigned f2tf(float f) {
    unsigned r;
    asm("cvt.rna.tf32.f32 %0, %1;" : "=r"(r) : "f"(f));
    return r;
}
__device__ __forceinline__ float f2tff(float f) {
    return __uint_as_float(f2tf(f));
}
__device__ __forceinline__ void ldsm4(unsigned& r0, unsigned& r1, unsigned& r2, unsigned& r3,
                                      unsigned addr) {
    asm volatile("ldmatrix.sync.aligned.m8n8.x4.shared.b16 {%0,%1,%2,%3}, [%4];"
                 : "=r"(r0), "=r"(r1), "=r"(r2), "=r"(r3) : "r"(addr));
}
__device__ __forceinline__ void mma8(float* d, const unsigned* a, const unsigned* b) {
    asm volatile("mma.sync.aligned.m16n8k8.row.col.f32.tf32.tf32.f32 "
                 "{%0,%1,%2,%3},{%4,%5,%6,%7},{%8,%9},{%0,%1,%2,%3};"
                 : "+f"(d[0]), "+f"(d[1]), "+f"(d[2]), "+f"(d[3])
                 : "r"(a[0]), "r"(a[1]), "r"(a[2]), "r"(a[3]), "r"(b[0]), "r"(b[1]));
}

// ---------------- preconvert weights to tf32 + concat biases -----------------
__global__ void preconv(const float* __restrict__ Wq, const float* __restrict__ Wk,
                        const float* __restrict__ Wv, const float* __restrict__ Ws,
                        const float* __restrict__ W1, const float* __restrict__ W2,
                        const float* __restrict__ W3, const float* __restrict__ Wc1,
                        const float* __restrict__ Wc2,
                        const float* __restrict__ bq, const float* __restrict__ bk,
                        const float* __restrict__ bv, const float* __restrict__ bs)
{
    int i = blockIdx.x * 256 + threadIdx.x;
    if (i < WTF_TOT) {
        float v;
        if (i < OFF_W1) {
            int wsel = i >> 16, idx = i & 65535;
            const float* src = (wsel == 0) ? Wq : (wsel == 1) ? Wk : (wsel == 2) ? Wv : Ws;
            v = src[idx];
        } else if (i < OFF_W2)  v = W1[i - OFF_W1];
        else if (i < OFF_W3)    v = W2[i - OFF_W2];
        else if (i < OFF_WC1)   v = W3[i - OFF_W3];
        else if (i < OFF_WC2)   v = Wc1[i - OFF_WC1];
        else                    v = Wc2[i - OFF_WC2];
        g_wtf[i] = f2tff(v);
    } else if (i < WTF_TOT + QS) {
        int j = i - WTF_TOT;
        int sel = j >> 8, idx = j & 255;
        const float* src = (sel == 0) ? bq : (sel == 1) ? bk : (sel == 2) ? bv : bs;
        g_bcat[j] = src[idx];
    }
}

// ---------------- init --------------------------------------------------------
__global__ void init_kernel() {
    int i = blockIdx.x * blockDim.x + threadIdx.x;
    if (i < NN) g_deg[i] = 0;
    if (i < HID * 2) {
        g_stats1[i] = 0.f;
        g_stats2[i] = 0.f;
    }
}

// ---------------- CSR build (parallel scan) -------------------------------------
__global__ void count_deg(const int* __restrict__ ei) {
    int e = blockIdx.x * blockDim.x + threadIdx.x;
    if (e >= EE) return;
    atomicAdd(&g_deg[ei[EE + e]], 1);
}

__global__ void __launch_bounds__(256)
deg_block_sums() {
    int i = blockIdx.x * 256 + threadIdx.x;
    int v = (i < NN) ? g_deg[i] : 0;
#pragma unroll
    for (int o = 16; o; o >>= 1) v += __shfl_xor_sync(0xFFFFFFFFu, v, o);
    __shared__ int ws[8];
    if ((threadIdx.x & 31) == 0) ws[threadIdx.x >> 5] = v;
    __syncthreads();
    if (threadIdx.x < 8) {
        int s = ws[threadIdx.x];
#pragma unroll
        for (int o = 4; o; o >>= 1) s += __shfl_xor_sync(0xFFu, s, o);
        if (threadIdx.x == 0) g_bsum[blockIdx.x] = s;
    }
}

__global__ void __launch_bounds__(256)
scan_bsums() {
    __shared__ int sm[256];
    int t = threadIdx.x;
    int v = (t < NBLK) ? g_bsum[t] : 0;
    sm[t] = v;
    __syncthreads();
#pragma unroll
    for (int s = 1; s < 256; s <<= 1) {
        int u = (t >= s) ? sm[t - s] : 0;
        __syncthreads();
        sm[t] += u;
        __syncthreads();
    }
    if (t < NBLK) g_bpref[t] = sm[t] - v;   // exclusive
}

__global__ void __launch_bounds__(256)
write_offsets() {
    __shared__ int sm[256];
    int t = threadIdx.x;
    int i = blockIdx.x * 256 + t;
    int v = (i < NN) ? g_deg[i] : 0;
    sm[t] = v;
    __syncthreads();
#pragma unroll
    for (int s = 1; s < 256; s <<= 1) {
        int u = (t >= s) ? sm[t - s] : 0;
        __syncthreads();
        sm[t] += u;
        __syncthreads();
    }
    if (i < NN) {
        int off = g_bpref[blockIdx.x] + sm[t];
        g_off[i + 1] = off;
        g_cursor[i] = off - v;
    }
    if (i == 0) g_off[0] = 0;
}

__global__ void scatter_edges(const int* __restrict__ ei) {
    int e = blockIdx.x * blockDim.x + threadIdx.x;
    if (e >= EE) return;
    int src = ei[e];
    int dst = ei[EE + e];
    int pos = atomicAdd(&g_cursor[dst], 1);
    g_csr_src[pos] = src;
}

// ---------------- fused attention: warp per (dst, head), online softmax --------
__global__ void __launch_bounds__(256)
attn_fused()
{
    int widx = blockIdx.x * 8 + (threadIdx.x >> 5);
    if (widx >= NN * 2) return;
    int nid = widx >> 1;
    int h = widx & 1;
    int lane = threadIdx.x & 31;

    float4 q4 = *(const float4*)(g_qkvs + (size_t)nid * QS + h * 128 + lane * 4);
    q4.x *= 0.08838834764831845f; q4.y *= 0.08838834764831845f;
    q4.z *= 0.08838834764831845f; q4.w *= 0.08838834764831845f;

    int beg = g_off[nid], end = g_off[nid + 1];
    if (beg == end) return;

    float m = -1e30f, d = 0.f;
    float ax = 0.f, ay = 0.f, az = 0.f, aw = 0.f;

    for (int j = beg; j < end; j++) {
        int src = g_csr_src[j];
        const float* kp = g_qkvs + (size_t)src * QS + 256 + h * 128 + lane * 4;
        float4 k4 = *(const float4*)kp;
        float4 v4 = *(const float4*)(kp + 256);
        float l = q4.x * k4.x + q4.y * k4.y + q4.z * k4.z + q4.w * k4.w;
#pragma unroll
        for (int o = 16; o; o >>= 1) l += __shfl_xor_sync(0xFFFFFFFFu, l, o);
        if (l > m) {
            float s = __expf(m - l);
            d = d * s + 1.f;
            ax = ax * s + v4.x; ay = ay * s + v4.y;
            az = az * s + v4.z; aw = aw * s + v4.w;
            m = l;
        } else {
            float w = __expf(l - m);
            d += w;
            ax += w * v4.x; ay += w * v4.y;
            az += w * v4.z; aw += w * v4.w;
        }
    }

    float inv = 1.f / fmaxf(d, 1e-16f);
    float* op = g_qkvs + (size_t)nid * QS + 768 + h * 128 + lane * 4;
    float4 o = *(const float4*)op;
    o.x += ax * inv; o.y += ay * inv; o.z += az * inv; o.w += aw * inv;
    *(float4*)op = o;
}

// ---------------- GEMM: C[M,N] = A[M,K] @ Btf[N,K]^T (+bias) ------------------
// AP=true: A already tf32-rounded in gmem -> pure cp.async both operands.
// AP=false: A raw fp32 -> register-staged cvt path.
// flags low 3 bits: 0=bias, 1=bias+relu, 2=no bias + column stats,
//                   3=C=alpha*C+beta*(acc+bias); bit 3 (8): round stores to tf32.
template<bool AP>
__global__ void __launch_bounds__(256, 2)
gemm(const float* __restrict__ A, int lda,
     const float* __restrict__ Btf,
     const float* __restrict__ bias,
     float* __restrict__ C, int ldc,
     int M, int N, int K, int flags,
     float* __restrict__ stats,
     const float* __restrict__ alpha, const float* __restrict__ beta)
{
    extern __shared__ float sm[];
    const unsigned ASZ = 128 * 36 * 4;          // bytes per stage (one tile)
    const unsigned B_OFF = 2 * ASZ;
    float* AsF = sm;
    unsigned s_base = (unsigned)__cvta_generic_to_shared(sm);

    const int tid = threadIdx.x, lane = tid & 31, w = tid >> 5;
    const int m0 = blockIdx.y * 128, n0 = blockIdx.x * 128;
    const int wm = (w & 3) * 32, wn = (w >> 2) * 64;
    const int g = lane >> 2, tg = lane & 3;
    const int cr = tid >> 3, cc = (tid & 7) * 4;
    const int mi4 = lane >> 3, rr = lane & 7;
    const unsigned frag_off = (((mi4 & 1) * 8 + rr) * 36 + (mi4 >> 1) * 4) * 4;

    float acc[2][8][4];
#pragma unroll
    for (int a = 0; a < 2; a++)
#pragma unroll
        for (int b = 0; b < 8; b++)
#pragma unroll
            for (int c = 0; c < 4; c++) acc[a][b][c] = 0.f;

    float4 ap[4];

#define LOAD_A(K0)                                                              \
    {                                                                           \
        _Pragma("unroll")                                                       \
        for (int t = 0; t < 4; t++) {                                           \
            int row = m0 + cr + t * 32;                                         \
            ap[t] = (row < M) ? *(const float4*)(A + (size_t)row * lda + (K0) + cc) \
                              : make_float4(0.f, 0.f, 0.f, 0.f);                \
        }                                                                       \
    }
#define STS_A(ST)                                                               \
    {                                                                           \
        _Pragma("unroll")                                                       \
        for (int t = 0; t < 4; t++) {                                           \
            uint4 u;                                                            \
            u.x = f2tf(ap[t].x); u.y = f2tf(ap[t].y);                           \
            u.z = f2tf(ap[t].z); u.w = f2tf(ap[t].w);                           \
            *(uint4*)(AsF + (ST) * 128 * 36 + (cr + t * 32) * 36 + cc) = u;     \
        }                                                                       \
    }
#define CP_A(K0, ST)                                                            \
    {                                                                           \
        _Pragma("unroll")                                                       \
        for (int t = 0; t < 4; t++) {                                           \
            int row = cr + t * 32;                                              \
            int grow = m0 + row;                                                \
            int pred = (grow < M) ? 16 : 0;                                     \
            int srow = (grow < M) ? grow : (M - 1);                             \
            unsigned dst = s_base + (ST) * ASZ + (row * 36 + cc) * 4;           \
            const float* src = A + (size_t)srow * lda + (K0) + cc;              \
            asm volatile("cp.async.cg.shared.global [%0], [%1], 16, %2;"        \
                         :: "r"(dst), "l"(src), "r"(pred));                     \
        }                                                                       \
    }
#define CP_B(K0, ST)                                                            \
    {                                                                           \
        _Pragma("unroll")                                                       \
        for (int t = 0; t < 4; t++) {                                           \
            int row = cr + t * 32;                                              \
            int nrow = n0 + row;                                                \
            int pred = (nrow < N) ? 16 : 0;                                     \
            int srow = (nrow < N) ? nrow : (N - 1);                             \
            unsigned dst = s_base + B_OFF + (ST) * ASZ + (row * 36 + cc) * 4;   \
            const float* src = Btf + (size_t)srow * K + (K0) + cc;              \
            asm volatile("cp.async.cg.shared.global [%0], [%1], 16, %2;"        \
                         :: "r"(dst), "l"(src), "r"(pred));                     \
        }                                                                       \
    }
#define COMPUTE(CUR)                                                            \
    {                                                                           \
        const unsigned aB = s_base + (CUR) * ASZ + wm * 144 + frag_off;         \
        const unsigned bB = s_base + B_OFF + (CUR) * ASZ + wn * 144 + frag_off; \
        _Pragma("unroll")                                                       \
        for (int ks = 0; ks < 4; ks++) {                                        \
            unsigned a0[4], a1[4], bf[8][2];                                    \
            ldsm4(a0[0], a0[1], a0[2], a0[3], aB + ks * 32);                    \
            ldsm4(a1[0], a1[1], a1[2], a1[3], aB + 16 * 144 + ks * 32);         \
            _Pragma("unroll")                                                   \
            for (int p = 0; p < 4; p++) {                                       \
                unsigned r0, r1, r2, r3;                                        \
                ldsm4(r0, r1, r2, r3, bB + p * 16 * 144 + ks * 32);             \
                bf[2 * p][0] = r0; bf[2 * p + 1][0] = r1;                       \
                bf[2 * p][1] = r2; bf[2 * p + 1][1] = r3;                       \
            }                                                                   \
            _Pragma("unroll")                                                   \
            for (int nj = 0; nj < 8; nj++) {                                    \
                mma8(acc[0][nj], a0, bf[nj]);                                   \
                mma8(acc[1][nj], a1, bf[nj]);                                   \
            }                                                                   \
        }                                                                       \
    }

    const int T = K >> 5;

    if (AP) {
        // pure cp.async double buffer; one commit group per stage (A+B)
        CP_A(0, 0); CP_B(0, 0);
        asm volatile("cp.async.commit_group;");
        for (int it = 0; it < T; ++it) {
            const int cur = it & 1;
            if (it + 1 < T) {
                CP_A((it + 1) * 32, cur ^ 1); CP_B((it + 1) * 32, cur ^ 1);
                asm volatile("cp.async.commit_group;");
                asm volatile("cp.async.wait_group 1;");
            } else {
                asm volatile("cp.async.wait_group 0;");
            }
            __syncthreads();
            COMPUTE(cur);
            __syncthreads();
        }
    } else {
        LOAD_A(0);
        CP_B(0, 0);
        asm volatile("cp.async.commit_group;");
        STS_A(0);
        asm volatile("cp.async.wait_group 0;");
        __syncthreads();
        for (int it = 0; it < T; ++it) {
            const int cur = it & 1, nxt = cur ^ 1;
            if (it + 1 < T) {
                LOAD_A((it + 1) * 32);
                CP_B((it + 1) * 32, nxt);
                asm volatile("cp.async.commit_group;");
            }
            COMPUTE(cur);
            if (it + 1 < T) {
                STS_A(nxt);
                asm volatile("cp.async.wait_group 0;");
            }
            __syncthreads();
        }
    }

    // ---- epilogue ----
    const int fbase = flags & 7;
    const bool rnd = (flags & 8) != 0;
    float alp = 0.f, bet = 0.f;
    if (fbase == 3) { alp = alpha[0]; bet = beta[0]; }

#pragma unroll
    for (int mi = 0; mi < 2; mi++) {
        int r0 = m0 + wm + mi * 16 + g;
        int r1 = r0 + 8;
#pragma unroll
        for (int nj = 0; nj < 8; nj++) {
            int gc = n0 + wn + nj * 8 + 2 * tg;
            if (gc >= N) continue;
            float bx = 0.f, by = 0.f;
            if (fbase != 2) { bx = bias[gc]; by = bias[gc + 1]; }
            float2 v0 = make_float2(acc[mi][nj][0] + bx, acc[mi][nj][1] + by);
            float2 v1 = make_float2(acc[mi][nj][2] + bx, acc[mi][nj][3] + by);
            if (fbase == 1) {
                v0.x = fmaxf(v0.x, 0.f); v0.y = fmaxf(v0.y, 0.f);
                v1.x = fmaxf(v1.x, 0.f); v1.y = fmaxf(v1.y, 0.f);
            }
            if (fbase == 3) {
                if (r0 < M) {
                    float2 o = *(float2*)(C + (size_t)r0 * ldc + gc);
                    v0.x = alp * o.x + bet * v0.x; v0.y = alp * o.y + bet * v0.y;
                }
                if (r1 < M) {
                    float2 o = *(float2*)(C + (size_t)r1 * ldc + gc);
                    v1.x = alp * o.x + bet * v1.x; v1.y = alp * o.y + bet * v1.y;
                }
            }
            if (rnd) {
                v0.x = f2tff(v0.x); v0.y = f2tff(v0.y);
                v1.x = f2tff(v1.x); v1.y = f2tff(v1.y);
            }
            if (r0 < M) *(float2*)(C + (size_t)r0 * ldc + gc) = v0;
            if (r1 < M) *(float2*)(C + (size_t)r1 * ldc + gc) = v1;
        }
    }

    if (fbase == 2) {
#pragma unroll
        for (int nj = 0; nj < 8; nj++) {
            int gc = n0 + wn + nj * 8 + 2 * tg;
            float sx = acc[0][nj][0] + acc[0][nj][2] + acc[1][nj][0] + acc[1][nj][2];
            float sy = acc[0][nj][1] + acc[0][nj][3] + acc[1][nj][1] + acc[1][nj][3];
            float qx = acc[0][nj][0] * acc[0][nj][0] + acc[0][nj][2] * acc[0][nj][2]
                     + acc[1][nj][0] * acc[1][nj][0] + acc[1][nj][2] * acc[1][nj][2];
            float qy = acc[0][nj][1] * acc[0][nj][1] + acc[0][nj][3] * acc[0][nj][3]
                     + acc[1][nj][1] * acc[1][nj][1] + acc[1][nj][3] * acc[1][nj][3];
#pragma unroll
            for (int o = 4; o < 32; o <<= 1) {
                sx += __shfl_xor_sync(0xFFFFFFFFu, sx, o);
                sy += __shfl_xor_sync(0xFFFFFFFFu, sy, o);
                qx += __shfl_xor_sync(0xFFFFFFFFu, qx, o);
                qy += __shfl_xor_sync(0xFFFFFFFFu, qy, o);
            }
            if (lane < 4) redAdd4(&stats[gc * 2], sx, qx, sy, qy);
        }
    }
#undef LOAD_A
#undef STS_A
#undef CP_A
#undef CP_B
#undef COMPUTE
}

// ---------------- batchnorm ----------------------------------------------------
__global__ void bn_finalize(const float* __restrict__ stats,
                            float* __restrict__ mu, float* __restrict__ rsig)
{
    int c = threadIdx.x + blockIdx.x * blockDim.x;
    if (c >= HID) return;
    float m = stats[c * 2] * (1.f / NN);
    float var = stats[c * 2 + 1] * (1.f / NN) - m * m;
    mu[c] = m;
    rsig[c] = rsqrtf(var + 1e-5f);
}

// applies BN+sigmoid and stores tf32-rounded (sole consumer is a GEMM)
__global__ void bn_apply_sigmoid(float* __restrict__ X,
                                 const float* __restrict__ mu, const float* __restrict__ rsig,
                                 const float* __restrict__ g, const float* __restrict__ be)
{
    size_t i = (size_t)blockIdx.x * blockDim.x + threadIdx.x;
    if (i >= (size_t)NN * HID) return;
    int c = (int)(i & (HID - 1));
    float x = X[i];
    float y = (x - mu[c]) * rsig[c] * g[c] + be[c];
    X[i] = f2tff(1.f / (1.f + expf(-y)));
}

// ---------------- launch --------------------------------------------------------
extern "C" void kernel_launch(void* const* d_in, const int* in_sizes, int n_in,
                              void* d_out, int out_size)
{
    const float* x_gsage = (const float*)d_in[0];
    const int*   ei      = (const int*)d_in[1];
    const float* x_mlp   = (const float*)d_in[2];
    const float* Wq = (const float*)d_in[3];  const float* bq = (const float*)d_in[4];
    const float* Wk = (const float*)d_in[5];  const float* bk = (const float*)d_in[6];
    const float* Wv = (const float*)d_in[7];  const float* bv = (const float*)d_in[8];
    const float* Ws = (const float*)d_in[9];  const float* bs = (const float*)d_in[10];
    const float* W1 = (const float*)d_in[11];
    const float* g1 = (const float*)d_in[13]; const float* be1 = (const float*)d_in[14];
    const float* W2 = (const float*)d_in[15];
    const float* g2 = (const float*)d_in[17]; const float* be2 = (const float*)d_in[18];
    const float* W3 = (const float*)d_in[19]; const float* b3 = (const float*)d_in[20];
    const float* alpha = (const float*)d_in[21];
    const float* beta  = (const float*)d_in[22];
    const float* Wc1 = (const float*)d_in[23]; const float* bc1 = (const float*)d_in[24];
    const float* Wc2 = (const float*)d_in[25]; const float* bc2 = (const float*)d_in[26];
    float* out = (float*)d_out;

    float *qkvs, *h1, *h2, *wtf, *bcat;
    float *stats1, *stats2, *mu1, *rsig1, *mu2, *rsig2;
    cudaGetSymbolAddress((void**)&qkvs, g_qkvs);
    cudaGetSymbolAddress((void**)&h1, g_h1);
    cudaGetSymbolAddress((void**)&h2, g_h2);
    cudaGetSymbolAddress((void**)&wtf, g_wtf);
    cudaGetSymbolAddress((void**)&bcat, g_bcat);
    cudaGetSymbolAddress((void**)&stats1, g_stats1);
    cudaGetSymbolAddress((void**)&stats2, g_stats2);
    cudaGetSymbolAddress((void**)&mu1, g_mu1);
    cudaGetSymbolAddress((void**)&rsig1, g_rsig1);
    cudaGetSymbolAddress((void**)&mu2, g_mu2);
    cudaGetSymbolAddress((void**)&rsig2, g_rsig2);

    static bool attr_set = false;
    if (!attr_set) {
        cudaFuncSetAttribute(gemm<false>, cudaFuncAttributeMaxDynamicSharedMemorySize, 73728);
        cudaFuncSetAttribute(gemm<true>,  cudaFuncAttributeMaxDynamicSharedMemorySize, 73728);
        attr_set = true;
    }
    const int SMB = 73728;
    const int MB = (NN + 127) / 128;
    dim3 blk(256);

    preconv<<<(WTF_TOT + QS + 255) / 256, blk>>>(Wq, Wk, Wv, Ws, W1, W2, W3, Wc1, Wc2,
                                                 bq, bk, bv, bs);
    init_kernel<<<(NN + 255) / 256, blk>>>();

    // CSR build (parallel scan)
    count_deg<<<(EE + 255) / 256, blk>>>(ei);
    deg_block_sums<<<NBLK, blk>>>();
    scan_bsums<<<1, blk>>>();
    write_offsets<<<NBLK, blk>>>();
    scatter_edges<<<(EE + 255) / 256, blk>>>(ei);

    // fused q|k|v|skip projection (N=1024); raw fp32 A
    gemm<false><<<dim3(8, MB), blk, SMB>>>(x_gsage, 256, wtf + OFF_QKVS, bcat, qkvs, QS,
                                           NN, 1024, 256, 0, nullptr, nullptr, nullptr);

    // fused attention (online softmax, no atomics)
    attn_fused<<<(NN * 2 + 7) / 8, blk>>>();

    // MLP branch; raw fp32 A, fused stats
    gemm<false><<<dim3(4, MB), blk, SMB>>>(x_mlp, 256, wtf + OFF_W1, nullptr, h1, HID,
                                           NN, HID, 256, 2, stats1, nullptr, nullptr);
    bn_finalize<<<2, blk>>>(stats1, mu1, rsig1);
    bn_apply_sigmoid<<<((size_t)NN * HID + 255) / 256, blk>>>(h1, mu1, rsig1, g1, be1);

    // h1 now tf32-rounded -> pure cp.async GEMM
    gemm<true><<<dim3(4, MB), blk, SMB>>>(h1, HID, wtf + OFF_W2, nullptr, h2, HID,
                                          NN, HID, HID, 2, stats2, nullptr, nullptr);
    bn_finalize<<<2, blk>>>(stats2, mu2, rsig2);
    bn_apply_sigmoid<<<((size_t)NN * HID + 255) / 256, blk>>>(h2, mu2, rsig2, g2, be2);

    // W3 with fused alpha/beta combine, in place into hg; round output (feeds Wc1)
    gemm<true><<<dim3(2, MB), blk, SMB>>>(h2, HID, wtf + OFF_W3, b3, qkvs + 768, QS,
                                          NN, HC, HID, 3 | 8, nullptr, alpha, beta);

    // classifier; Wc1 output rounded (feeds Wc2)
    gemm<true><<<dim3(4, MB), blk, SMB>>>(qkvs + 768, QS, wtf + OFF_WC1, bc1, h1, HID,
                                          NN, HID, HC, 1 | 8, nullptr, nullptr, nullptr);
    gemm<true><<<dim3(1, MB), blk, SMB>>>(h1, HID, wtf + OFF_WC2, bc2, out, NCLS,
                                          NN, NCLS, HID, 0, nullptr, nullptr, nullptr);
}

// round 6
// speedup vs baseline: 4.4410x; 1.3526x over previous
#include <cuda_runtime.h>
#include <cuda_fp16.h>
#include <math.h>
#include <stdint.h>

#define NN 50000
#define EE 800000
#define HID 512
#define HC 256
#define NCLS 40
#define QS 1024     // interleaved qkv+skip stride (halfs)
#define NBLK 196    // ceil(NN/256)

// weight-buffer offsets (fp16-converted, row-major [N][K])
#define OFF_QKVS 0
#define OFF_W1   262144
#define OFF_W2   393216
#define OFF_W3   655360
#define OFF_WC1  786432
#define OFF_WC2  917504
#define WTF_TOT  937984

// ---------------- scratch ----------------------------------------------------
__device__ __half g_qkvs[(size_t)NN * QS];  // q[0,256) k[256,512) v[512,768) hg[768,1024)
__device__ __half g_h1[(size_t)NN * HID];
__device__ __half g_h2[(size_t)NN * HID];
__device__ int    g_deg[NN];
__device__ int    g_off[NN + 1];
__device__ int    g_cursor[NN];
__device__ int    g_csr_src[EE];
__device__ int    g_bsum[256];
__device__ int    g_bpref[256];
__device__ float  g_stats1[HID * 2];        // interleaved sum, sumsq
__device__ float  g_stats2[HID * 2];
__device__ float  g_mu1[HID], g_rsig1[HID], g_mu2[HID], g_rsig2[HID];
__device__ __half g_wh[WTF_TOT];
__device__ float  g_bcat[QS];

// ---------------- helpers ----------------------------------------------------
__device__ __forceinline__ void redAdd4(float* p, float a, float b, float c, float d) {
    asm volatile("red.global.add.v4.f32 [%0], {%1,%2,%3,%4};"
                 :: "l"(p), "f"(a), "f"(b), "f"(c), "f"(d) : "memory");
}
__device__ __forceinline__ float4 ld4h(const __half* p) {
    uint2 u = *(const uint2*)p;
    __half2 h0 = *(__half2*)&u.x, h1 = *(__half2*)&u.y;
    float2 a = __half22float2(h0), b = __half22float2(h1);
    return make_float4(a.x, a.y, b.x, b.y);
}
__device__ __forceinline__ void st4h(__half* p, float4 v) {
    uint2 u;
    __half2 h0 = __float22half2_rn(make_float2(v.x, v.y));
    __half2 h1 = __float22half2_rn(make_float2(v.z, v.w));
    u.x = *(unsigned*)&h0; u.y = *(unsigned*)&h1;
    *(uint2*)p = u;
}
__device__ __forceinline__ void ldsm4(unsigned& r0, unsigned& r1, unsigned& r2, unsigned& r3,
                                      unsigned addr) {
    asm volatile("ldmatrix.sync.aligned.m8n8.x4.shared.b16 {%0,%1,%2,%3}, [%4];"
                 : "=r"(r0), "=r"(r1), "=r"(r2), "=r"(r3) : "r"(addr));
}
__device__ __forceinline__ void mma16(float* d, const unsigned* a, const unsigned* b) {
    asm volatile("mma.sync.aligned.m16n8k16.row.col.f32.f16.f16.f32 "
                 "{%0,%1,%2,%3},{%4,%5,%6,%7},{%8,%9},{%0,%1,%2,%3};"
                 : "+f"(d[0]), "+f"(d[1]), "+f"(d[2]), "+f"(d[3])
                 : "r"(a[0]), "r"(a[1]), "r"(a[2]), "r"(a[3]), "r"(b[0]), "r"(b[1]));
}

// ---------------- preconvert weights to fp16 + concat biases -----------------
__global__ void preconv(const float* __restrict__ Wq, const float* __restrict__ Wk,
                        const float* __restrict__ Wv, const float* __restrict__ Ws,
                        const float* __restrict__ W1, const float* __restrict__ W2,
                        const float* __restrict__ W3, const float* __restrict__ Wc1,
                        const float* __restrict__ Wc2,
                        const float* __restrict__ bq, const float* __restrict__ bk,
                        const float* __restrict__ bv, const float* __restrict__ bs)
{
    int i = blockIdx.x * 256 + threadIdx.x;
    if (i < WTF_TOT) {
        float v;
        if (i < OFF_W1) {
            int wsel = i >> 16, idx = i & 65535;
            const float* src = (wsel == 0) ? Wq : (wsel == 1) ? Wk : (wsel == 2) ? Wv : Ws;
            v = src[idx];
        } else if (i < OFF_W2)  v = W1[i - OFF_W1];
        else if (i < OFF_W3)    v = W2[i - OFF_W2];
        else if (i < OFF_WC1)   v = W3[i - OFF_W3];
        else if (i < OFF_WC2)   v = Wc1[i - OFF_WC1];
        else                    v = Wc2[i - OFF_WC2];
        g_wh[i] = __float2half_rn(v);
    } else if (i < WTF_TOT + QS) {
        int j = i - WTF_TOT;
        int sel = j >> 8, idx = j & 255;
        const float* src = (sel == 0) ? bq : (sel == 1) ? bk : (sel == 2) ? bv : bs;
        g_bcat[j] = src[idx];
    }
}

// ---------------- init --------------------------------------------------------
__global__ void init_kernel() {
    int i = blockIdx.x * blockDim.x + threadIdx.x;
    if (i < NN) g_deg[i] = 0;
    if (i < HID * 2) {
        g_stats1[i] = 0.f;
        g_stats2[i] = 0.f;
    }
}

// ---------------- CSR build (parallel scan) -------------------------------------
__global__ void count_deg(const int* __restrict__ ei) {
    int e = blockIdx.x * blockDim.x + threadIdx.x;
    if (e >= EE) return;
    atomicAdd(&g_deg[ei[EE + e]], 1);
}

__global__ void __launch_bounds__(256)
deg_block_sums() {
    int i = blockIdx.x * 256 + threadIdx.x;
    int v = (i < NN) ? g_deg[i] : 0;
#pragma unroll
    for (int o = 16; o; o >>= 1) v += __shfl_xor_sync(0xFFFFFFFFu, v, o);
    __shared__ int ws[8];
    if ((threadIdx.x & 31) == 0) ws[threadIdx.x >> 5] = v;
    __syncthreads();
    if (threadIdx.x < 8) {
        int s = ws[threadIdx.x];
#pragma unroll
        for (int o = 4; o; o >>= 1) s += __shfl_xor_sync(0xFFu, s, o);
        if (threadIdx.x == 0) g_bsum[blockIdx.x] = s;
    }
}

__global__ void __launch_bounds__(256)
scan_bsums() {
    __shared__ int sm[256];
    int t = threadIdx.x;
    int v = (t < NBLK) ? g_bsum[t] : 0;
    sm[t] = v;
    __syncthreads();
#pragma unroll
    for (int s = 1; s < 256; s <<= 1) {
        int u = (t >= s) ? sm[t - s] : 0;
        __syncthreads();
        sm[t] += u;
        __syncthreads();
    }
    if (t < NBLK) g_bpref[t] = sm[t] - v;   // exclusive
}

__global__ void __launch_bounds__(256)
write_offsets() {
    __shared__ int sm[256];
    int t = threadIdx.x;
    int i = blockIdx.x * 256 + t;
    int v = (i < NN) ? g_deg[i] : 0;
    sm[t] = v;
    __syncthreads();
#pragma unroll
    for (int s = 1; s < 256; s <<= 1) {
        int u = (t >= s) ? sm[t - s] : 0;
        __syncthreads();
        sm[t] += u;
        __syncthreads();
    }
    if (i < NN) {
        int off = g_bpref[blockIdx.x] + sm[t];
        g_off[i + 1] = off;
        g_cursor[i] = off - v;
    }
    if (i == 0) g_off[0] = 0;
}

__global__ void scatter_edges(const int* __restrict__ ei) {
    int e = blockIdx.x * blockDim.x + threadIdx.x;
    if (e >= EE) return;
    int src = ei[e];
    int dst = ei[EE + e];
    int pos = atomicAdd(&g_cursor[dst], 1);
    g_csr_src[pos] = src;
}

// ---------------- fused attention: warp per (dst, head), online softmax --------
__global__ void __launch_bounds__(256)
attn_fused()
{
    int widx = blockIdx.x * 8 + (threadIdx.x >> 5);
    if (widx >= NN * 2) return;
    int nid = widx >> 1;
    int h = widx & 1;
    int lane = threadIdx.x & 31;

    float4 q4 = ld4h(g_qkvs + (size_t)nid * QS + h * 128 + lane * 4);
    q4.x *= 0.08838834764831845f; q4.y *= 0.08838834764831845f;
    q4.z *= 0.08838834764831845f; q4.w *= 0.08838834764831845f;

    int beg = g_off[nid], end = g_off[nid + 1];
    if (beg == end) return;

    float m = -1e30f, d = 0.f;
    float ax = 0.f, ay = 0.f, az = 0.f, aw = 0.f;

    for (int j = beg; j < end; j++) {
        int src = g_csr_src[j];
        const __half* kp = g_qkvs + (size_t)src * QS + 256 + h * 128 + lane * 4;
        float4 k4 = ld4h(kp);
        float4 v4 = ld4h(kp + 256);
        float l = q4.x * k4.x + q4.y * k4.y + q4.z * k4.z + q4.w * k4.w;
#pragma unroll
        for (int o = 16; o; o >>= 1) l += __shfl_xor_sync(0xFFFFFFFFu, l, o);
        if (l > m) {
            float s = __expf(m - l);
            d = d * s + 1.f;
            ax = ax * s + v4.x; ay = ay * s + v4.y;
            az = az * s + v4.z; aw = aw * s + v4.w;
            m = l;
        } else {
            float w = __expf(l - m);
            d += w;
            ax += w * v4.x; ay += w * v4.y;
            az += w * v4.z; aw += w * v4.w;
        }
    }

    float inv = 1.f / fmaxf(d, 1e-16f);
    __half* op = g_qkvs + (size_t)nid * QS + 768 + h * 128 + lane * 4;
    float4 o = ld4h(op);
    o.x += ax * inv; o.y += ay * inv; o.z += az * inv; o.w += aw * inv;
    st4h(op, o);
}

// ---------------- fp16 tensor GEMM: C[M,N] = A[M,K] @ Bh[N,K]^T (+bias) --------
// AF=true: A fp16 in gmem (pure cp.async). AF=false: A fp32 (reg-staged cvt).
// flags low 3 bits: 0=bias, 1=bias+relu, 2=no bias + column stats,
//                   3=C=alpha*C+beta*(acc+bias). bit 4 (16): C is fp16.
template<bool AF>
__global__ void __launch_bounds__(256, 2)
gemm(const void* __restrict__ Aptr, int lda,
     const __half* __restrict__ Bh,
     const float* __restrict__ bias,
     void* __restrict__ Cptr, int ldc,
     int M, int N, int K, int flags,
     float* __restrict__ stats,
     const float* __restrict__ alpha, const float* __restrict__ beta)
{
    extern __shared__ __half smh[];
    const unsigned ASZ = 128 * 40 * 2;          // bytes per stage per operand
    const unsigned B_OFF = 2 * ASZ;
    unsigned s_base = (unsigned)__cvta_generic_to_shared(smh);

    const int tid = threadIdx.x, lane = tid & 31, w = tid >> 5;
    const int m0 = blockIdx.y * 128, n0 = blockIdx.x * 128;
    const int wm = (w & 3) * 32, wn = (w >> 2) * 64;
    const int g = lane >> 2, tg = lane & 3;

    // copy mapping: each thread covers 16 contiguous halfs of one row
    const int cr = tid >> 1;             // 0..127 row
    const int ch = (tid & 1) * 16;       // half-col base (0 or 16)

    // fragment lane offsets
    const unsigned a_loff = ((lane & 15) * 40 + (lane >> 4) * 8) * 2;
    const int bm = lane >> 3;
    const unsigned b_loff = (((bm >> 1) * 8 + (lane & 7)) * 40 + (bm & 1) * 8) * 2;

    float acc[2][8][4];
#pragma unroll
    for (int a = 0; a < 2; a++)
#pragma unroll
        for (int b = 0; b < 8; b++)
#pragma unroll
            for (int c = 0; c < 4; c++) acc[a][b][c] = 0.f;

    const float* Af = (const float*)Aptr;
    const __half* Ah = (const __half*)Aptr;
    float4 ap[4];

#define LOAD_A(K0)                                                              \
    {                                                                           \
        int grow = m0 + cr;                                                     \
        const float* src = Af + (size_t)((grow < M) ? grow : (M - 1)) * lda + (K0) + ch; \
        _Pragma("unroll")                                                       \
        for (int t = 0; t < 4; t++) ap[t] = *(const float4*)(src + t * 4);      \
        if (grow >= M) { ap[0] = ap[1] = ap[2] = ap[3] = make_float4(0,0,0,0); } \
    }
#define STS_A(ST)                                                               \
    {                                                                           \
        uint4 u0, u1;                                                           \
        __half2 h;                                                              \
        h = __float22half2_rn(make_float2(ap[0].x, ap[0].y)); u0.x = *(unsigned*)&h; \
        h = __float22half2_rn(make_float2(ap[0].z, ap[0].w)); u0.y = *(unsigned*)&h; \
        h = __float22half2_rn(make_float2(ap[1].x, ap[1].y)); u0.z = *(unsigned*)&h; \
        h = __float22half2_rn(make_float2(ap[1].z, ap[1].w)); u0.w = *(unsigned*)&h; \
        h = __float22half2_rn(make_float2(ap[2].x, ap[2].y)); u1.x = *(unsigned*)&h; \
        h = __float22half2_rn(make_float2(ap[2].z, ap[2].w)); u1.y = *(unsigned*)&h; \
        h = __float22half2_rn(make_float2(ap[3].x, ap[3].y)); u1.z = *(unsigned*)&h; \
        h = __float22half2_rn(make_float2(ap[3].z, ap[3].w)); u1.w = *(unsigned*)&h; \
        __half* dst = smh + (ST) * 128 * 40 + cr * 40 + ch;                     \
        *(uint4*)dst = u0;                                                      \
        *(uint4*)(dst + 8) = u1;                                                \
    }
#define CP_A(K0, ST)                                                            \
    {                                                                           \
        int grow = m0 + cr;                                                     \
        int pred = (grow < M) ? 16 : 0;                                         \
        const __half* src = Ah + (size_t)((grow < M) ? grow : (M - 1)) * lda + (K0) + ch; \
        unsigned dst = s_base + (ST) * ASZ + (cr * 40 + ch) * 2;                \
        asm volatile("cp.async.cg.shared.global [%0], [%1], 16, %2;"            \
                     :: "r"(dst), "l"(src), "r"(pred));                         \
        asm volatile("cp.async.cg.shared.global [%0], [%1], 16, %2;"            \
                     :: "r"(dst + 16), "l"(src + 8), "r"(pred));                \
    }
#define CP_B(K0, ST)                                                            \
    {                                                                           \
        int nrow = n0 + cr;                                                     \
        int pred = (nrow < N) ? 16 : 0;                                         \
        const __half* src = Bh + (size_t)((nrow < N) ? nrow : (N - 1)) * K + (K0) + ch; \
        unsigned dst = s_base + B_OFF + (ST) * ASZ + (cr * 40 + ch) * 2;        \
        asm volatile("cp.async.cg.shared.global [%0], [%1], 16, %2;"            \
                     :: "r"(dst), "l"(src), "r"(pred));                         \
        asm volatile("cp.async.cg.shared.global [%0], [%1], 16, %2;"            \
                     :: "r"(dst + 16), "l"(src + 8), "r"(pred));                \
    }
#define COMPUTE(CUR)                                                            \
    {                                                                           \
        const unsigned aS = s_base + (CUR) * ASZ + wm * 80 + a_loff;            \
        const unsigned bS = s_base + B_OFF + (CUR) * ASZ + wn * 80 + b_loff;    \
        _Pragma("unroll")                                                       \
        for (int kk = 0; kk < 32; kk += 16) {                                   \
            unsigned a0[4], a1[4], bf[8][2];                                    \
            ldsm4(a0[0], a0[1], a0[2], a0[3], aS + kk * 2);                     \
            ldsm4(a1[0], a1[1], a1[2], a1[3], aS + 16 * 80 + kk * 2);           \
            _Pragma("unroll")                                                   \
            for (int p = 0; p < 4; p++) {                                       \
                unsigned r0, r1, r2, r3;                                        \
                ldsm4(r0, r1, r2, r3, bS + p * 16 * 80 + kk * 2);               \
                bf[2 * p][0] = r0;     bf[2 * p][1] = r1;                       \
                bf[2 * p + 1][0] = r2; bf[2 * p + 1][1] = r3;                   \
            }                                                                   \
            _Pragma("unroll")                                                   \
            for (int nj = 0; nj < 8; nj++) {                                    \
                mma16(acc[0][nj], a0, bf[nj]);                                  \
                mma16(acc[1][nj], a1, bf[nj]);                                  \
            }                                                                   \
        }                                                                       \
    }

    const int T = K >> 5;

    if (AF) {
        CP_A(0, 0); CP_B(0, 0);
        asm volatile("cp.async.commit_group;");
        for (int it = 0; it < T; ++it) {
            const int cur = it & 1;
            if (it + 1 < T) {
                CP_A((it + 1) * 32, cur ^ 1); CP_B((it + 1) * 32, cur ^ 1);
                asm volatile("cp.async.commit_group;");
                asm volatile("cp.async.wait_group 1;");
            } else {
                asm volatile("cp.async.wait_group 0;");
            }
            __syncthreads();
            COMPUTE(cur);
            __syncthreads();
        }
    } else {
        LOAD_A(0);
        CP_B(0, 0);
        asm volatile("cp.async.commit_group;");
        STS_A(0);
        asm volatile("cp.async.wait_group 0;");
        __syncthreads();
        for (int it = 0; it < T; ++it) {
            const int cur = it & 1, nxt = cur ^ 1;
            if (it + 1 < T) {
                LOAD_A((it + 1) * 32);
                CP_B((it + 1) * 32, nxt);
                asm volatile("cp.async.commit_group;");
            }
            COMPUTE(cur);
            if (it + 1 < T) {
                STS_A(nxt);
                asm volatile("cp.async.wait_group 0;");
            }
            __syncthreads();
        }
    }

    // ---- epilogue ----
    const int fbase = flags & 7;
    const bool ch16 = (flags & 16) != 0;
    float alp = 0.f, bet = 0.f;
    if (fbase == 3) { alp = alpha[0]; bet = beta[0]; }
    float* Cf = (float*)Cptr;
    __half* Chf = (__half*)Cptr;

#pragma unroll
    for (int mi = 0; mi < 2; mi++) {
        int r0 = m0 + wm + mi * 16 + g;
        int r1 = r0 + 8;
#pragma unroll
        for (int nj = 0; nj < 8; nj++) {
            int gc = n0 + wn + nj * 8 + 2 * tg;
            if (gc >= N) continue;
            float bx = 0.f, by = 0.f;
            if (fbase != 2) { bx = bias[gc]; by = bias[gc + 1]; }
            float2 v0 = make_float2(acc[mi][nj][0] + bx, acc[mi][nj][1] + by);
            float2 v1 = make_float2(acc[mi][nj][2] + bx, acc[mi][nj][3] + by);
            if (fbase == 1) {
                v0.x = fmaxf(v0.x, 0.f); v0.y = fmaxf(v0.y, 0.f);
                v1.x = fmaxf(v1.x, 0.f); v1.y = fmaxf(v1.y, 0.f);
            }
            if (fbase == 3) {
                if (r0 < M) {
                    float2 o = __half22float2(*(__half2*)(Chf + (size_t)r0 * ldc + gc));
                    v0.x = alp * o.x + bet * v0.x; v0.y = alp * o.y + bet * v0.y;
                }
                if (r1 < M) {
                    float2 o = __half22float2(*(__half2*)(Chf + (size_t)r1 * ldc + gc));
                    v1.x = alp * o.x + bet * v1.x; v1.y = alp * o.y + bet * v1.y;
                }
            }
            if (ch16) {
                if (r0 < M) *(__half2*)(Chf + (size_t)r0 * ldc + gc) = __float22half2_rn(v0);
                if (r1 < M) *(__half2*)(Chf + (size_t)r1 * ldc + gc) = __float22half2_rn(v1);
            } else {
                if (r0 < M) *(float2*)(Cf + (size_t)r0 * ldc + gc) = v0;
                if (r1 < M) *(float2*)(Cf + (size_t)r1 * ldc + gc) = v1;
            }
        }
    }

    if (fbase == 2) {
#pragma unroll
        for (int nj = 0; nj < 8; nj++) {
            int gc = n0 + wn + nj * 8 + 2 * tg;
            float sx = acc[0][nj][0] + acc[0][nj][2] + acc[1][nj][0] + acc[1][nj][2];
            float sy = acc[0][nj][1] + acc[0][nj][3] + acc[1][nj][1] + acc[1][nj][3];
            float qx = acc[0][nj][0] * acc[0][nj][0] + acc[0][nj][2] * acc[0][nj][2]
                     + acc[1][nj][0] * acc[1][nj][0] + acc[1][nj][2] * acc[1][nj][2];
            float qy = acc[0][nj][1] * acc[0][nj][1] + acc[0][nj][3] * acc[0][nj][3]
                     + acc[1][nj][1] * acc[1][nj][1] + acc[1][nj][3] * acc[1][nj][3];
#pragma unroll
            for (int o = 4; o < 32; o <<= 1) {
                sx += __shfl_xor_sync(0xFFFFFFFFu, sx, o);
                sy += __shfl_xor_sync(0xFFFFFFFFu, sy, o);
                qx += __shfl_xor_sync(0xFFFFFFFFu, qx, o);
                qy += __shfl_xor_sync(0xFFFFFFFFu, qy, o);
            }
            if (lane < 4) redAdd4(&stats[gc * 2], sx, qx, sy, qy);
        }
    }
#undef LOAD_A
#undef STS_A
#undef CP_A
#undef CP_B
#undef COMPUTE
}

// ---------------- batchnorm ----------------------------------------------------
__global__ void bn_finalize(const float* __restrict__ stats,
                            float* __restrict__ mu, float* __restrict__ rsig)
{
    int c = threadIdx.x + blockIdx.x * blockDim.x;
    if (c >= HID) return;
    float m = stats[c * 2] * (1.f / NN);
    float var = stats[c * 2 + 1] * (1.f / NN) - m * m;
    mu[c] = m;
    rsig[c] = rsqrtf(var + 1e-5f);
}

__global__ void bn_apply_sigmoid(__half* __restrict__ X,
                                 const float* __restrict__ mu, const float* __restrict__ rsig,
                                 const float* __restrict__ g, const float* __restrict__ be)
{
    size_t i = (size_t)blockIdx.x * blockDim.x + threadIdx.x;
    if (i >= (size_t)NN * HID / 4) return;
    size_t base = i * 4;
    int c = (int)(base & (HID - 1));
    float4 x = ld4h(X + base);
    float4 y;
    y.x = (x.x - mu[c])     * rsig[c]     * g[c]     + be[c];
    y.y = (x.y - mu[c + 1]) * rsig[c + 1] * g[c + 1] + be[c + 1];
    y.z = (x.z - mu[c + 2]) * rsig[c + 2] * g[c + 2] + be[c + 2];
    y.w = (x.w - mu[c + 3]) * rsig[c + 3] * g[c + 3] + be[c + 3];
    y.x = 1.f / (1.f + expf(-y.x));
    y.y = 1.f / (1.f + expf(-y.y));
    y.z = 1.f / (1.f + expf(-y.z));
    y.w = 1.f / (1.f + expf(-y.w));
    st4h(X + base, y);
}

// ---------------- launch --------------------------------------------------------
extern "C" void kernel_launch(void* const* d_in, const int* in_sizes, int n_in,
                              void* d_out, int out_size)
{
    const float* x_gsage = (const float*)d_in[0];
    const int*   ei      = (const int*)d_in[1];
    const float* x_mlp   = (const float*)d_in[2];
    const float* Wq = (const float*)d_in[3];  const float* bq = (const float*)d_in[4];
    const float* Wk = (const float*)d_in[5];  const float* bk = (const float*)d_in[6];
    const float* Wv = (const float*)d_in[7];  const float* bv = (const float*)d_in[8];
    const float* Ws = (const float*)d_in[9];  const float* bs = (const float*)d_in[10];
    const float* W1 = (const float*)d_in[11];
    const float* g1 = (const float*)d_in[13]; const float* be1 = (const float*)d_in[14];
    const float* W2 = (const float*)d_in[15];
    const float* g2 = (const float*)d_in[17]; const float* be2 = (const float*)d_in[18];
    const float* W3 = (const float*)d_in[19]; const float* b3 = (const float*)d_in[20];
    const float* alpha = (const float*)d_in[21];
    const float* beta  = (const float*)d_in[22];
    const float* Wc1 = (const float*)d_in[23]; const float* bc1 = (const float*)d_in[24];
    const float* Wc2 = (const float*)d_in[25]; const float* bc2 = (const float*)d_in[26];
    float* out = (float*)d_out;

    __half *qkvs, *h1, *h2, *wh;
    float *bcat, *stats1, *stats2, *mu1, *rsig1, *mu2, *rsig2;
    cudaGetSymbolAddress((void**)&qkvs, g_qkvs);
    cudaGetSymbolAddress((void**)&h1, g_h1);
    cudaGetSymbolAddress((void**)&h2, g_h2);
    cudaGetSymbolAddress((void**)&wh, g_wh);
    cudaGetSymbolAddress((void**)&bcat, g_bcat);
    cudaGetSymbolAddress((void**)&stats1, g_stats1);
    cudaGetSymbolAddress((void**)&stats2, g_stats2);
    cudaGetSymbolAddress((void**)&mu1, g_mu1);
    cudaGetSymbolAddress((void**)&rsig1, g_rsig1);
    cudaGetSymbolAddress((void**)&mu2, g_mu2);
    cudaGetSymbolAddress((void**)&rsig2, g_rsig2);

    const int SMB = 40960;
    const int MB = (NN + 127) / 128;
    dim3 blk(256);

    preconv<<<(WTF_TOT + QS + 255) / 256, blk>>>(Wq, Wk, Wv, Ws, W1, W2, W3, Wc1, Wc2,
                                                 bq, bk, bv, bs);
    init_kernel<<<(NN + 255) / 256, blk>>>();

    // CSR build (parallel scan)
    count_deg<<<(EE + 255) / 256, blk>>>(ei);
    deg_block_sums<<<NBLK, blk>>>();
    scan_bsums<<<1, blk>>>();
    write_offsets<<<NBLK, blk>>>();
    scatter_edges<<<(EE + 255) / 256, blk>>>(ei);

    // fused q|k|v|skip projection (N=1024); fp32 A, fp16 C
    gemm<false><<<dim3(8, MB), blk, SMB>>>(x_gsage, 256, wh + OFF_QKVS, bcat, qkvs, QS,
                                           NN, 1024, 256, 0 | 16, nullptr, nullptr, nullptr);

    // fused attention (online softmax, no atomics)
    attn_fused<<<(NN * 2 + 7) / 8, blk>>>();

    // MLP branch; fp32 A, fused stats, fp16 C
    gemm<false><<<dim3(4, MB), blk, SMB>>>(x_mlp, 256, wh + OFF_W1, nullptr, h1, HID,
                                           NN, HID, 256, 2 | 16, stats1, nullptr, nullptr);
    bn_finalize<<<2, blk>>>(stats1, mu1, rsig1);
    bn_apply_sigmoid<<<((size_t)NN * HID / 4 + 255) / 256, blk>>>(h1, mu1, rsig1, g1, be1);

    gemm<true><<<dim3(4, MB), blk, SMB>>>(h1, HID, wh + OFF_W2, nullptr, h2, HID,
                                          NN, HID, HID, 2 | 16, stats2, nullptr, nullptr);
    bn_finalize<<<2, blk>>>(stats2, mu2, rsig2);
    bn_apply_sigmoid<<<((size_t)NN * HID / 4 + 255) / 256, blk>>>(h2, mu2, rsig2, g2, be2);

    // W3 with fused alpha/beta combine, in place into hg (fp16)
    gemm<true><<<dim3(2, MB), blk, SMB>>>(h2, HID, wh + OFF_W3, b3, qkvs + 768, QS,
                                          NN, HC, HID, 3 | 16, nullptr, alpha, beta);

    // classifier
    gemm<true><<<dim3(4, MB), blk, SMB>>>(qkvs + 768, QS, wh + OFF_WC1, bc1, h1, HID,
                                          NN, HID, HC, 1 | 16, nullptr, nullptr, nullptr);
    gemm<true><<<dim3(1, MB), blk, SMB>>>(h1, HID, wh + OFF_WC2, bc2, out, NCLS,
                                          NN, NCLS, HID, 0, nullptr, nullptr, nullptr);
}

// round 7
// speedup vs baseline: 4.8284x; 1.0872x over previous
#include <cuda_runtime.h>
#include <cuda_fp16.h>
#include <math.h>
#include <stdint.h>

#define NN 50000
#define EE 800000
#define HID 512
#define HC 256
#define NCLS 40
#define QS 1024     // interleaved qkv+skip stride (halfs)
#define NBLK 196    // ceil(NN/256)

// weight-buffer offsets (fp16-converted, row-major [N][K])
#define OFF_QKVS 0
#define OFF_W1   262144
#define OFF_W2   393216
#define OFF_W3   655360
#define OFF_WC1  786432
#define OFF_WC2  917504
#define WTF_TOT  937984

// ---------------- scratch ----------------------------------------------------
__device__ __half g_qkvs[(size_t)NN * QS];  // q[0,256) k[256,512) v[512,768) hg[768,1024)
__device__ __half g_h1[(size_t)NN * HID];
__device__ __half g_h2[(size_t)NN * HID];
__device__ int    g_deg[NN];
__device__ int    g_off[NN + 1];
__device__ int    g_cursor[NN];
__device__ int    g_csr_src[EE];
__device__ int    g_bsum[256];
__device__ int    g_bpref[256];
__device__ float  g_stats1[HID * 2];        // interleaved sum, sumsq
__device__ float  g_stats2[HID * 2];
__device__ float  g_mu1[HID], g_rsig1[HID], g_mu2[HID], g_rsig2[HID];
__device__ __half g_wh[WTF_TOT];
__device__ float  g_bcat[QS];

// ---------------- helpers ----------------------------------------------------
__device__ __forceinline__ void redAdd4(float* p, float a, float b, float c, float d) {
    asm volatile("red.global.add.v4.f32 [%0], {%1,%2,%3,%4};"
                 :: "l"(p), "f"(a), "f"(b), "f"(c), "f"(d) : "memory");
}
__device__ __forceinline__ float4 ld4h(const __half* p) {
    uint2 u = *(const uint2*)p;
    __half2 h0 = *(__half2*)&u.x, h1 = *(__half2*)&u.y;
    float2 a = __half22float2(h0), b = __half22float2(h1);
    return make_float4(a.x, a.y, b.x, b.y);
}
__device__ __forceinline__ void st4h(__half* p, float4 v) {
    uint2 u;
    __half2 h0 = __float22half2_rn(make_float2(v.x, v.y));
    __half2 h1 = __float22half2_rn(make_float2(v.z, v.w));
    u.x = *(unsigned*)&h0; u.y = *(unsigned*)&h1;
    *(uint2*)p = u;
}
__device__ __forceinline__ void cvt8(float* f, uint4 u) {
    __half2* h = (__half2*)&u;
#pragma unroll
    for (int i = 0; i < 4; i++) {
        float2 t = __half22float2(h[i]);
        f[2 * i] = t.x; f[2 * i + 1] = t.y;
    }
}
__device__ __forceinline__ void ldsm4(unsigned& r0, unsigned& r1, unsigned& r2, unsigned& r3,
                                      unsigned addr) {
    asm volatile("ldmatrix.sync.aligned.m8n8.x4.shared.b16 {%0,%1,%2,%3}, [%4];"
                 : "=r"(r0), "=r"(r1), "=r"(r2), "=r"(r3) : "r"(addr));
}
__device__ __forceinline__ void mma16(float* d, const unsigned* a, const unsigned* b) {
    asm volatile("mma.sync.aligned.m16n8k16.row.col.f32.f16.f16.f32 "
                 "{%0,%1,%2,%3},{%4,%5,%6,%7},{%8,%9},{%0,%1,%2,%3};"
                 : "+f"(d[0]), "+f"(d[1]), "+f"(d[2]), "+f"(d[3])
                 : "r"(a[0]), "r"(a[1]), "r"(a[2]), "r"(a[3]), "r"(b[0]), "r"(b[1]));
}

// ---------------- preconvert weights to fp16 + concat biases -----------------
__global__ void preconv(const float* __restrict__ Wq, const float* __restrict__ Wk,
                        const float* __restrict__ Wv, const float* __restrict__ Ws,
                        const float* __restrict__ W1, const float* __restrict__ W2,
                        const float* __restrict__ W3, const float* __restrict__ Wc1,
                        const float* __restrict__ Wc2,
                        const float* __restrict__ bq, const float* __restrict__ bk,
                        const float* __restrict__ bv, const float* __restrict__ bs)
{
    int i = blockIdx.x * 256 + threadIdx.x;
    if (i < WTF_TOT) {
        float v;
        if (i < OFF_W1) {
            int wsel = i >> 16, idx = i & 65535;
            const float* src = (wsel == 0) ? Wq : (wsel == 1) ? Wk : (wsel == 2) ? Wv : Ws;
            v = src[idx];
        } else if (i < OFF_W2)  v = W1[i - OFF_W1];
        else if (i < OFF_W3)    v = W2[i - OFF_W2];
        else if (i < OFF_WC1)   v = W3[i - OFF_W3];
        else if (i < OFF_WC2)   v = Wc1[i - OFF_WC1];
        else                    v = Wc2[i - OFF_WC2];
        g_wh[i] = __float2half_rn(v);
    } else if (i < WTF_TOT + QS) {
        int j = i - WTF_TOT;
        int sel = j >> 8, idx = j & 255;
        const float* src = (sel == 0) ? bq : (sel == 1) ? bk : (sel == 2) ? bv : bs;
        g_bcat[j] = src[idx];
    }
}

__global__ void init_stats() {
    int i = blockIdx.x * blockDim.x + threadIdx.x;
    if (i < HID * 2) {
        g_stats1[i] = 0.f;
        g_stats2[i] = 0.f;
    }
}

// ---------------- CSR build (parallel scan) -------------------------------------
__global__ void zero_deg() {
    int i = blockIdx.x * blockDim.x + threadIdx.x;
    if (i < NN) g_deg[i] = 0;
}

__global__ void count_deg(const int* __restrict__ ei) {
    int e = blockIdx.x * blockDim.x + threadIdx.x;
    if (e >= EE) return;
    atomicAdd(&g_deg[ei[EE + e]], 1);
}

__global__ void __launch_bounds__(256)
deg_block_sums() {
    int i = blockIdx.x * 256 + threadIdx.x;
    int v = (i < NN) ? g_deg[i] : 0;
#pragma unroll
    for (int o = 16; o; o >>= 1) v += __shfl_xor_sync(0xFFFFFFFFu, v, o);
    __shared__ int ws[8];
    if ((threadIdx.x & 31) == 0) ws[threadIdx.x >> 5] = v;
    __syncthreads();
    if (threadIdx.x < 8) {
        int s = ws[threadIdx.x];
#pragma unroll
        for (int o = 4; o; o >>= 1) s += __shfl_xor_sync(0xFFu, s, o);
        if (threadIdx.x == 0) g_bsum[blockIdx.x] = s;
    }
}

__global__ void __launch_bounds__(256)
scan_bsums() {
    __shared__ int sm[256];
    int t = threadIdx.x;
    int v = (t < NBLK) ? g_bsum[t] : 0;
    sm[t] = v;
    __syncthreads();
#pragma unroll
    for (int s = 1; s < 256; s <<= 1) {
        int u = (t >= s) ? sm[t - s] : 0;
        __syncthreads();
        sm[t] += u;
        __syncthreads();
    }
    if (t < NBLK) g_bpref[t] = sm[t] - v;   // exclusive
}

__global__ void __launch_bounds__(256)
write_offsets() {
    __shared__ int sm[256];
    int t = threadIdx.x;
    int i = blockIdx.x * 256 + t;
    int v = (i < NN) ? g_deg[i] : 0;
    sm[t] = v;
    __syncthreads();
#pragma unroll
    for (int s = 1; s < 256; s <<= 1) {
        int u = (t >= s) ? sm[t - s] : 0;
        __syncthreads();
        sm[t] += u;
        __syncthreads();
    }
    if (i < NN) {
        int off = g_bpref[blockIdx.x] + sm[t];
        g_off[i + 1] = off;
        g_cursor[i] = off - v;
    }
    if (i == 0) g_off[0] = 0;
}

__global__ void scatter_edges(const int* __restrict__ ei) {
    int e = blockIdx.x * blockDim.x + threadIdx.x;
    if (e >= EE) return;
    int src = ei[e];
    int dst = ei[EE + e];
    int pos = atomicAdd(&g_cursor[dst], 1);
    g_csr_src[pos] = src;
}

// ---------------- fused attention: warp per node (both heads), online softmax --
__global__ void __launch_bounds__(256)
attn_fused()
{
    int nid = blockIdx.x * 8 + (threadIdx.x >> 5);
    if (nid >= NN) return;
    int lane = threadIdx.x & 31;
    int head = lane >> 4;            // lanes 0-15 head0, 16-31 head1
    int c = (lane & 15) * 8;         // 8 halfs per lane

    const size_t row = (size_t)nid * QS;
    float q[8];
    cvt8(q, *(const uint4*)(g_qkvs + row + head * 128 + c));
#pragma unroll
    for (int i = 0; i < 8; i++) q[i] *= 0.08838834764831845f;

    int beg = g_off[nid], end = g_off[nid + 1];
    if (beg == end) return;

    float m = -1e30f, d = 0.f;
    float acc[8];
#pragma unroll
    for (int i = 0; i < 8; i++) acc[i] = 0.f;

    for (int j0 = beg; j0 < end; j0 += 32) {
        int idx = j0 + lane;
        int sreg = (idx < end) ? g_csr_src[idx] : 0;
        int cnt = min(32, end - j0);
        for (int t = 0; t < cnt; t++) {
            int src = __shfl_sync(0xFFFFFFFFu, sreg, t);
            const __half* kp = g_qkvs + (size_t)src * QS + 256 + head * 128 + c;
            float kf[8], vf[8];
            cvt8(kf, *(const uint4*)kp);
            cvt8(vf, *(const uint4*)(kp + 256));
            float l = q[0] * kf[0] + q[1] * kf[1] + q[2] * kf[2] + q[3] * kf[3]
                    + q[4] * kf[4] + q[5] * kf[5] + q[6] * kf[6] + q[7] * kf[7];
#pragma unroll
            for (int o = 8; o; o >>= 1) l += __shfl_xor_sync(0xFFFFFFFFu, l, o);
            // branchless online softmax update (uniform within 16-lane group)
            float mn = fmaxf(m, l);
            float s = __expf(m - mn);
            float w = __expf(l - mn);
            d = d * s + w;
#pragma unroll
            for (int i = 0; i < 8; i++) acc[i] = acc[i] * s + w * vf[i];
            m = mn;
        }
    }

    float inv = 1.f / fmaxf(d, 1e-16f);
    __half* op = g_qkvs + row + 768 + head * 128 + c;
    float o[8];
    cvt8(o, *(const uint4*)op);
    uint4 u;
    __half2* uh = (__half2*)&u;
#pragma unroll
    for (int i = 0; i < 4; i++)
        uh[i] = __float22half2_rn(make_float2(o[2 * i] + acc[2 * i] * inv,
                                              o[2 * i + 1] + acc[2 * i + 1] * inv));
    *(uint4*)op = u;
}

// ---------------- fp16 tensor GEMM: C[M,N] = A[M,K] @ Bh[N,K]^T (+bias) --------
// AF=true: A fp16 in gmem (pure cp.async). AF=false: A fp32 (reg-staged cvt).
// flags low 3 bits: 0=bias, 1=bias+relu, 2=no bias + column stats,
//                   3=C=alpha*C+beta*(acc+bias). bit 4 (16): C is fp16.
template<bool AF>
__global__ void __launch_bounds__(256, 2)
gemm(const void* __restrict__ Aptr, int lda,
     const __half* __restrict__ Bh,
     const float* __restrict__ bias,
     void* __restrict__ Cptr, int ldc,
     int M, int N, int K, int flags,
     float* __restrict__ stats,
     const float* __restrict__ alpha, const float* __restrict__ beta)
{
    extern __shared__ __half smh[];
    const unsigned ASZ = 128 * 40 * 2;          // bytes per stage per operand
    const unsigned B_OFF = 2 * ASZ;
    unsigned s_base = (unsigned)__cvta_generic_to_shared(smh);

    const int tid = threadIdx.x, lane = tid & 31, w = tid >> 5;
    const int m0 = blockIdx.y * 128, n0 = blockIdx.x * 128;
    const int wm = (w & 3) * 32, wn = (w >> 2) * 64;
    const int g = lane >> 2, tg = lane & 3;

    const int cr = tid >> 1;             // copy row 0..127
    const int ch = (tid & 1) * 16;       // half-col base

    const unsigned a_loff = ((lane & 15) * 40 + (lane >> 4) * 8) * 2;
    const int bm = lane >> 3;
    const unsigned b_loff = (((bm >> 1) * 8 + (lane & 7)) * 40 + (bm & 1) * 8) * 2;

    float acc[2][8][4];
#pragma unroll
    for (int a = 0; a < 2; a++)
#pragma unroll
        for (int b = 0; b < 8; b++)
#pragma unroll
            for (int c = 0; c < 4; c++) acc[a][b][c] = 0.f;

    const float* Af = (const float*)Aptr;
    const __half* Ah = (const __half*)Aptr;
    float4 ap[4];

#define LOAD_A(K0)                                                              \
    {                                                                           \
        int grow = m0 + cr;                                                     \
        const float* src = Af + (size_t)((grow < M) ? grow : (M - 1)) * lda + (K0) + ch; \
        _Pragma("unroll")                                                       \
        for (int t = 0; t < 4; t++) ap[t] = *(const float4*)(src + t * 4);      \
        if (grow >= M) { ap[0] = ap[1] = ap[2] = ap[3] = make_float4(0,0,0,0); } \
    }
#define STS_A(ST)                                                               \
    {                                                                           \
        uint4 u0, u1;                                                           \
        __half2 h;                                                              \
        h = __float22half2_rn(make_float2(ap[0].x, ap[0].y)); u0.x = *(unsigned*)&h; \
        h = __float22half2_rn(make_float2(ap[0].z, ap[0].w)); u0.y = *(unsigned*)&h; \
        h = __float22half2_rn(make_float2(ap[1].x, ap[1].y)); u0.z = *(unsigned*)&h; \
        h = __float22half2_rn(make_float2(ap[1].z, ap[1].w)); u0.w = *(unsigned*)&h; \
        h = __float22half2_rn(make_float2(ap[2].x, ap[2].y)); u1.x = *(unsigned*)&h; \
        h = __float22half2_rn(make_float2(ap[2].z, ap[2].w)); u1.y = *(unsigned*)&h; \
        h = __float22half2_rn(make_float2(ap[3].x, ap[3].y)); u1.z = *(unsigned*)&h; \
        h = __float22half2_rn(make_float2(ap[3].z, ap[3].w)); u1.w = *(unsigned*)&h; \
        __half* dst = smh + (ST) * 128 * 40 + cr * 40 + ch;                     \
        *(uint4*)dst = u0;                                                      \
        *(uint4*)(dst + 8) = u1;                                                \
    }
#define CP_A(K0, ST)                                                            \
    {                                                                           \
        int grow = m0 + cr;                                                     \
        int pred = (grow < M) ? 16 : 0;                                         \
        const __half* src = Ah + (size_t)((grow < M) ? grow : (M - 1)) * lda + (K0) + ch; \
        unsigned dst = s_base + (ST) * ASZ + (cr * 40 + ch) * 2;                \
        asm volatile("cp.async.cg.shared.global [%0], [%1], 16, %2;"            \
                     :: "r"(dst), "l"(src), "r"(pred));                         \
        asm volatile("cp.async.cg.shared.global [%0], [%1], 16, %2;"            \
                     :: "r"(dst + 16), "l"(src + 8), "r"(pred));                \
    }
#define CP_B(K0, ST)                                                            \
    {                                                                           \
        int nrow = n0 + cr;                                                     \
        int pred = (nrow < N) ? 16 : 0;                                         \
        const __half* src = Bh + (size_t)((nrow < N) ? nrow : (N - 1)) * K + (K0) + ch; \
        unsigned dst = s_base + B_OFF + (ST) * ASZ + (cr * 40 + ch) * 2;        \
        asm volatile("cp.async.cg.shared.global [%0], [%1], 16, %2;"            \
                     :: "r"(dst), "l"(src), "r"(pred));                         \
        asm volatile("cp.async.cg.shared.global [%0], [%1], 16, %2;"            \
                     :: "r"(dst + 16), "l"(src + 8), "r"(pred));                \
    }
#define COMPUTE(CUR)                                                            \
    {                                                                           \
        const unsigned aS = s_base + (CUR) * ASZ + wm * 80 + a_loff;            \
        const unsigned bS = s_base + B_OFF + (CUR) * ASZ + wn * 80 + b_loff;    \
        _Pragma("unroll")                                                       \
        for (int kk = 0; kk < 32; kk += 16) {                                   \
            unsigned a0[4], a1[4], bf[8][2];                                    \
            ldsm4(a0[0], a0[1], a0[2], a0[3], aS + kk * 2);                     \
            ldsm4(a1[0], a1[1], a1[2], a1[3], aS + 16 * 80 + kk * 2);           \
            _Pragma("unroll")                                                   \
            for (int p = 0; p < 4; p++) {                                       \
                unsigned r0, r1, r2, r3;                                        \
                ldsm4(r0, r1, r2, r3, bS + p * 16 * 80 + kk * 2);               \
                bf[2 * p][0] = r0;     bf[2 * p][1] = r1;                       \
                bf[2 * p + 1][0] = r2; bf[2 * p + 1][1] = r3;                   \
            }                                                                   \
            _Pragma("unroll")                                                   \
            for (int nj = 0; nj < 8; nj++) {                                    \
                mma16(acc[0][nj], a0, bf[nj]);                                  \
                mma16(acc[1][nj], a1, bf[nj]);                                  \
            }                                                                   \
        }                                                                       \
    }

    const int T = K >> 5;

    if (AF) {
        CP_A(0, 0); CP_B(0, 0);
        asm volatile("cp.async.commit_group;");
        for (int it = 0; it < T; ++it) {
            const int cur = it & 1;
            if (it + 1 < T) {
                CP_A((it + 1) * 32, cur ^ 1); CP_B((it + 1) * 32, cur ^ 1);
                asm volatile("cp.async.commit_group;");
                asm volatile("cp.async.wait_group 1;");
            } else {
                asm volatile("cp.async.wait_group 0;");
            }
            __syncthreads();
            COMPUTE(cur);
            __syncthreads();
        }
    } else {
        LOAD_A(0);
        CP_B(0, 0);
        asm volatile("cp.async.commit_group;");
        STS_A(0);
        asm volatile("cp.async.wait_group 0;");
        __syncthreads();
        for (int it = 0; it < T; ++it) {
            const int cur = it & 1, nxt = cur ^ 1;
            if (it + 1 < T) {
                LOAD_A((it + 1) * 32);
                CP_B((it + 1) * 32, nxt);
                asm volatile("cp.async.commit_group;");
            }
            COMPUTE(cur);
            if (it + 1 < T) {
                STS_A(nxt);
                asm volatile("cp.async.wait_group 0;");
            }
            __syncthreads();
        }
    }

    // ---- epilogue ----
    const int fbase = flags & 7;
    const bool ch16 = (flags & 16) != 0;
    float alp = 0.f, bet = 0.f;
    if (fbase == 3) { alp = alpha[0]; bet = beta[0]; }
    float* Cf = (float*)Cptr;
    __half* Chf = (__half*)Cptr;

#pragma unroll
    for (int mi = 0; mi < 2; mi++) {
        int r0 = m0 + wm + mi * 16 + g;
        int r1 = r0 + 8;
#pragma unroll
        for (int nj = 0; nj < 8; nj++) {
            int gc = n0 + wn + nj * 8 + 2 * tg;
            if (gc >= N) continue;
            float bx = 0.f, by = 0.f;
            if (fbase != 2) { bx = bias[gc]; by = bias[gc + 1]; }
            float2 v0 = make_float2(acc[mi][nj][0] + bx, acc[mi][nj][1] + by);
            float2 v1 = make_float2(acc[mi][nj][2] + bx, acc[mi][nj][3] + by);
            if (fbase == 1) {
                v0.x = fmaxf(v0.x, 0.f); v0.y = fmaxf(v0.y, 0.f);
                v1.x = fmaxf(v1.x, 0.f); v1.y = fmaxf(v1.y, 0.f);
            }
            if (fbase == 3) {
                if (r0 < M) {
                    float2 o = __half22float2(*(__half2*)(Chf + (size_t)r0 * ldc + gc));
                    v0.x = alp * o.x + bet * v0.x; v0.y = alp * o.y + bet * v0.y;
                }
                if (r1 < M) {
                    float2 o = __half22float2(*(__half2*)(Chf + (size_t)r1 * ldc + gc));
                    v1.x = alp * o.x + bet * v1.x; v1.y = alp * o.y + bet * v1.y;
                }
            }
            if (ch16) {
                if (r0 < M) *(__half2*)(Chf + (size_t)r0 * ldc + gc) = __float22half2_rn(v0);
                if (r1 < M) *(__half2*)(Chf + (size_t)r1 * ldc + gc) = __float22half2_rn(v1);
            } else {
                if (r0 < M) *(float2*)(Cf + (size_t)r0 * ldc + gc) = v0;
                if (r1 < M) *(float2*)(Cf + (size_t)r1 * ldc + gc) = v1;
            }
        }
    }

    if (fbase == 2) {
#pragma unroll
        for (int nj = 0; nj < 8; nj++) {
            int gc = n0 + wn + nj * 8 + 2 * tg;
            float sx = acc[0][nj][0] + acc[0][nj][2] + acc[1][nj][0] + acc[1][nj][2];
            float sy = acc[0][nj][1] + acc[0][nj][3] + acc[1][nj][1] + acc[1][nj][3];
            float qx = acc[0][nj][0] * acc[0][nj][0] + acc[0][nj][2] * acc[0][nj][2]
                     + acc[1][nj][0] * acc[1][nj][0] + acc[1][nj][2] * acc[1][nj][2];
            float qy = acc[0][nj][1] * acc[0][nj][1] + acc[0][nj][3] * acc[0][nj][3]
                     + acc[1][nj][1] * acc[1][nj][1] + acc[1][nj][3] * acc[1][nj][3];
#pragma unroll
            for (int o = 4; o < 32; o <<= 1) {
                sx += __shfl_xor_sync(0xFFFFFFFFu, sx, o);
                sy += __shfl_xor_sync(0xFFFFFFFFu, sy, o);
                qx += __shfl_xor_sync(0xFFFFFFFFu, qx, o);
                qy += __shfl_xor_sync(0xFFFFFFFFu, qy, o);
            }
            if (lane < 4) redAdd4(&stats[gc * 2], sx, qx, sy, qy);
        }
    }
#undef LOAD_A
#undef STS_A
#undef CP_A
#undef CP_B
#undef COMPUTE
}

// ---------------- batchnorm ----------------------------------------------------
__global__ void bn_finalize(const float* __restrict__ stats,
                            float* __restrict__ mu, float* __restrict__ rsig)
{
    int c = threadIdx.x + blockIdx.x * blockDim.x;
    if (c >= HID) return;
    float m = stats[c * 2] * (1.f / NN);
    float var = stats[c * 2 + 1] * (1.f / NN) - m * m;
    mu[c] = m;
    rsig[c] = rsqrtf(var + 1e-5f);
}

__global__ void bn_apply_sigmoid(__half* __restrict__ X,
                                 const float* __restrict__ mu, const float* __restrict__ rsig,
                                 const float* __restrict__ g, const float* __restrict__ be)
{
    size_t i = (size_t)blockIdx.x * blockDim.x + threadIdx.x;
    if (i >= (size_t)NN * HID / 4) return;
    size_t base = i * 4;
    int c = (int)(base & (HID - 1));
    float4 x = ld4h(X + base);
    float4 y;
    y.x = (x.x - mu[c])     * rsig[c]     * g[c]     + be[c];
    y.y = (x.y - mu[c + 1]) * rsig[c + 1] * g[c + 1] + be[c + 1];
    y.z = (x.z - mu[c + 2]) * rsig[c + 2] * g[c + 2] + be[c + 2];
    y.w = (x.w - mu[c + 3]) * rsig[c + 3] * g[c + 3] + be[c + 3];
    y.x = 1.f / (1.f + expf(-y.x));
    y.y = 1.f / (1.f + expf(-y.y));
    y.z = 1.f / (1.f + expf(-y.z));
    y.w = 1.f / (1.f + expf(-y.w));
    st4h(X + base, y);
}

// ---------------- launch --------------------------------------------------------
extern "C" void kernel_launch(void* const* d_in, const int* in_sizes, int n_in,
                              void* d_out, int out_size)
{
    const float* x_gsage = (const float*)d_in[0];
    const int*   ei      = (const int*)d_in[1];
    const float* x_mlp   = (const float*)d_in[2];
    const float* Wq = (const float*)d_in[3];  const float* bq = (const float*)d_in[4];
    const float* Wk = (const float*)d_in[5];  const float* bk = (const float*)d_in[6];
    const float* Wv = (const float*)d_in[7];  const float* bv = (const float*)d_in[8];
    const float* Ws = (const float*)d_in[9];  const float* bs = (const float*)d_in[10];
    const float* W1 = (const float*)d_in[11];
    const float* g1 = (const float*)d_in[13]; const float* be1 = (const float*)d_in[14];
    const float* W2 = (const float*)d_in[15];
    const float* g2 = (const float*)d_in[17]; const float* be2 = (const float*)d_in[18];
    const float* W3 = (const float*)d_in[19]; const float* b3 = (const float*)d_in[20];
    const float* alpha = (const float*)d_in[21];
    const float* beta  = (const float*)d_in[22];
    const float* Wc1 = (const float*)d_in[23]; const float* bc1 = (const float*)d_in[24];
    const float* Wc2 = (const float*)d_in[25]; const float* bc2 = (const float*)d_in[26];
    float* out = (float*)d_out;

    __half *qkvs, *h1, *h2, *wh;
    float *bcat, *stats1, *stats2, *mu1, *rsig1, *mu2, *rsig2;
    cudaGetSymbolAddress((void**)&qkvs, g_qkvs);
    cudaGetSymbolAddress((void**)&h1, g_h1);
    cudaGetSymbolAddress((void**)&h2, g_h2);
    cudaGetSymbolAddress((void**)&wh, g_wh);
    cudaGetSymbolAddress((void**)&bcat, g_bcat);
    cudaGetSymbolAddress((void**)&stats1, g_stats1);
    cudaGetSymbolAddress((void**)&stats2, g_stats2);
    cudaGetSymbolAddress((void**)&mu1, g_mu1);
    cudaGetSymbolAddress((void**)&rsig1, g_rsig1);
    cudaGetSymbolAddress((void**)&mu2, g_mu2);
    cudaGetSymbolAddress((void**)&rsig2, g_rsig2);

    static cudaStream_t s1 = nullptr, s2 = nullptr;
    static cudaEvent_t evFork, evPre, evCSR, evMLP;
    if (!s1) {
        cudaStreamCreateWithFlags(&s1, cudaStreamNonBlocking);
        cudaStreamCreateWithFlags(&s2, cudaStreamNonBlocking);
        cudaEventCreateWithFlags(&evFork, cudaEventDisableTiming);
        cudaEventCreateWithFlags(&evPre,  cudaEventDisableTiming);
        cudaEventCreateWithFlags(&evCSR,  cudaEventDisableTiming);
        cudaEventCreateWithFlags(&evMLP,  cudaEventDisableTiming);
    }

    const int SMB = 40960;
    const int MB = (NN + 127) / 128;
    dim3 blk(256);

    // ---- fork s1: CSR build (independent of everything) ----
    cudaEventRecord(evFork, 0);
    cudaStreamWaitEvent(s1, evFork, 0);
    zero_deg<<<(NN + 255) / 256, blk, 0, s1>>>();
    count_deg<<<(EE + 255) / 256, blk, 0, s1>>>(ei);
    deg_block_sums<<<NBLK, blk, 0, s1>>>();
    scan_bsums<<<1, blk, 0, s1>>>();
    write_offsets<<<NBLK, blk, 0, s1>>>();
    scatter_edges<<<(EE + 255) / 256, blk, 0, s1>>>(ei);
    cudaEventRecord(evCSR, s1);

    // ---- main: preconv + stats init ----
    preconv<<<(WTF_TOT + QS + 255) / 256, blk>>>(Wq, Wk, Wv, Ws, W1, W2, W3, Wc1, Wc2,
                                                 bq, bk, bv, bs);
    init_stats<<<4, blk>>>();
    cudaEventRecord(evPre, 0);

    // ---- fork s2: MLP branch ----
    cudaStreamWaitEvent(s2, evPre, 0);
    gemm<false><<<dim3(4, MB), blk, SMB, s2>>>(x_mlp, 256, wh + OFF_W1, nullptr, h1, HID,
                                               NN, HID, 256, 2 | 16, stats1, nullptr, nullptr);
    bn_finalize<<<2, blk, 0, s2>>>(stats1, mu1, rsig1);
    bn_apply_sigmoid<<<((size_t)NN * HID / 4 + 255) / 256, blk, 0, s2>>>(h1, mu1, rsig1, g1, be1);
    gemm<true><<<dim3(4, MB), blk, SMB, s2>>>(h1, HID, wh + OFF_W2, nullptr, h2, HID,
                                              NN, HID, HID, 2 | 16, stats2, nullptr, nullptr);
    bn_finalize<<<2, blk, 0, s2>>>(stats2, mu2, rsig2);
    bn_apply_sigmoid<<<((size_t)NN * HID / 4 + 255) / 256, blk, 0, s2>>>(h2, mu2, rsig2, g2, be2);
    cudaEventRecord(evMLP, s2);

    // ---- main: GNN branch ----
    gemm<false><<<dim3(8, MB), blk, SMB>>>(x_gsage, 256, wh + OFF_QKVS, bcat, qkvs, QS,
                                           NN, 1024, 256, 0 | 16, nullptr, nullptr, nullptr);
    cudaStreamWaitEvent(0, evCSR, 0);
    attn_fused<<<(NN + 7) / 8, blk>>>();

    // ---- join: W3 needs h2 (s2) and hg (main) ----
    cudaStreamWaitEvent(0, evMLP, 0);
    gemm<true><<<dim3(2, MB), blk, SMB>>>(h2, HID, wh + OFF_W3, b3, qkvs + 768, QS,
                                          NN, HC, HID, 3 | 16, nullptr, alpha, beta);

    // classifier
    gemm<true><<<dim3(4, MB), blk, SMB>>>(qkvs + 768, QS, wh + OFF_WC1, bc1, h1, HID,
                                          NN, HID, HC, 1 | 16, nullptr, nullptr, nullptr);
    gemm<true><<<dim3(1, MB), blk, SMB>>>(h1, HID, wh + OFF_WC2, bc2, out, NCLS,
                                          NN, NCLS, HID, 0, nullptr, nullptr, nullptr);
}